// round 7
// baseline (speedup 1.0000x reference)
#include <cuda_runtime.h>
#include <cuda_bf16.h>
#include <math_constants.h>

#define Nn 50000
#define Ee 800000
#define DIN 128
#define HID 32
#define HEADS 8
#define F1 (HEADS*HID)   // 256

// ---------------- scratch (static device globals; no allocation) ----------------
__device__ float g_hs1[Nn*F1];     // layer1 source features  [N,256]
__device__ float g_agg[Nn*F1];     // layer1 output h         [N,256]
__device__ float g_hs2[Nn*HID];    // layer2 source features  [N,32]
__device__ float g_as1[Nn*HEADS], g_ad1[Nn*HEADS];
__device__ float g_as2[Nn], g_ad2[Nn];
__device__ float g_inv1[Nn*HEADS];          // per-node per-head 1/denominator
__device__ float g_inv2[Nn];
__device__ float g_Wsr1[HEADS*DIN], g_Wdr1[HEADS*DIN];   // [h][k] layout
__device__ float g_Wsr2[F1], g_Wdr2[F1];
__device__ int   g_src[Ee], g_dst[Ee];     // decoded edge index (int32)
__device__ int   g_deg[Nn];                // in-degree histogram
__device__ int   g_rowptr[Nn + 1];         // CSR row pointers (by dst)
__device__ int   g_cursor[Nn];             // fill cursors
__device__ int   g_esrc[Ee];               // CSR column (src) ids
__device__ int   g_edst[Ee];               // CSR dst id per position
__device__ float g_w1[Ee*HEADS];           // per-edge per-head weights (CSR order, unnormalized)
__device__ float g_w2[Ee];                 // layer-2 per-edge weights (CSR order, unnormalized)
__device__ int   g_bsum[64];               // scan block sums

__device__ __forceinline__ float leaky(float v) { return v > 0.f ? v : 0.2f * v; }

// ---------------- init: zero degree histogram ----------------
__global__ void init_kernel() {
    int i = blockIdx.x * blockDim.x + threadIdx.x;
    if (i < Nn) g_deg[i] = 0;
}

// ---------------- edge index decode (int32 OR little-endian int64) + histogram ----------------
__global__ void convert_idx(const int* __restrict__ raw) {
    bool is_i64 = true;
    #pragma unroll
    for (int i = 0; i < 16; i++)
        if (raw[2*i + 1] != 0) is_i64 = false;
    int e = blockIdx.x * blockDim.x + threadIdx.x;
    if (e >= Ee) return;
    int s, d;
    if (is_i64) { s = raw[2*e]; d = raw[2*(Ee + e)]; }
    else        { s = raw[e];   d = raw[Ee + e]; }
    g_src[e] = s;
    g_dst[e] = d;
    atomicAdd(&g_deg[d], 1);
}

// ---------------- hierarchical scan ----------------
__global__ void scan_blocks() {
    __shared__ int sm[1024];
    int gid = blockIdx.x * 1024 + threadIdx.x;
    int v = (gid < Nn) ? g_deg[gid] : 0;
    sm[threadIdx.x] = v;
    __syncthreads();
    for (int off = 1; off < 1024; off <<= 1) {
        int t = (threadIdx.x >= off) ? sm[threadIdx.x - off] : 0;
        __syncthreads();
        sm[threadIdx.x] += t;
        __syncthreads();
    }
    if (gid < Nn) g_rowptr[gid] = sm[threadIdx.x] - v;
    if (threadIdx.x == 1023) g_bsum[blockIdx.x] = sm[1023];
}

__global__ void scan_bsums(int nblocks) {
    __shared__ int sm[64];
    int v = (threadIdx.x < nblocks) ? g_bsum[threadIdx.x] : 0;
    sm[threadIdx.x] = v;
    __syncthreads();
    for (int off = 1; off < 64; off <<= 1) {
        int t = (threadIdx.x >= off) ? sm[threadIdx.x - off] : 0;
        __syncthreads();
        sm[threadIdx.x] += t;
        __syncthreads();
    }
    if (threadIdx.x < nblocks) g_bsum[threadIdx.x] = sm[threadIdx.x] - v;
}

__global__ void scan_add() {
    int gid = blockIdx.x * blockDim.x + threadIdx.x;
    if (gid < Nn) {
        int r = g_rowptr[gid] + g_bsum[gid >> 10];
        g_rowptr[gid] = r;
        g_cursor[gid] = r;
    }
    if (gid == 0) g_rowptr[Nn] = Ee;
}

// ---------------- CSR fill ----------------
__global__ void fill_kernel() {
    int e = blockIdx.x * blockDim.x + threadIdx.x;
    if (e >= Ee) return;
    int d = g_dst[e];
    int pos = atomicAdd(&g_cursor[d], 1);
    g_esrc[pos] = g_src[e];
    g_edst[pos] = d;
}

// ---------------- reduce attention weight vectors ----------------
__global__ void reduceW_kernel(const float* __restrict__ W1s, const float* __restrict__ W1d,
                               const float* __restrict__ a1s, const float* __restrict__ a1d,
                               const float* __restrict__ W2s, const float* __restrict__ W2d,
                               const float* __restrict__ a2s, const float* __restrict__ a2d) {
    int idx = blockIdx.x * blockDim.x + threadIdx.x;
    if (idx < HEADS*DIN) {
        int h = idx >> 7, k = idx & 127;
        float s = 0.f, d = 0.f;
        #pragma unroll
        for (int c = 0; c < HID; c++) {
            s += W1s[k*F1 + h*HID + c] * a1s[h*HID + c];
            d += W1d[k*F1 + h*HID + c] * a1d[h*HID + c];
        }
        g_Wsr1[h*DIN + k] = s;
        g_Wdr1[h*DIN + k] = d;
    } else if (idx < HEADS*DIN + F1) {
        int k = idx - HEADS*DIN;
        float s = 0.f, d = 0.f;
        #pragma unroll
        for (int c = 0; c < HID; c++) {
            s += W2s[k*HID + c] * a2s[c];
            d += W2d[k*HID + c] * a2d[c];
        }
        g_Wsr2[k] = s;
        g_Wdr2[k] = d;
    }
}

// ---------------- layer-1 GEMM: g_hs1 = x[N,128] @ W1_src[128,256] ----------------
__global__ void gemm1_kernel(const float* __restrict__ A, const float* __restrict__ B) {
    const int TK = 8;
    __shared__ float As[TK][132];
    __shared__ float Bs[TK][128];
    int bm = blockIdx.y * 128;
    int bn = blockIdx.x * 128;
    int tid = threadIdx.x;
    int tx = tid & 15;
    int ty = tid >> 4;
    float acc[8][8] = {};
    for (int k0 = 0; k0 < DIN; k0 += TK) {
        {
            int row = tid >> 1, kq = (tid & 1) * 4;
            int gr = bm + row;
            float4 v = make_float4(0.f, 0.f, 0.f, 0.f);
            if (gr < Nn) v = *reinterpret_cast<const float4*>(&A[gr*DIN + k0 + kq]);
            As[kq + 0][row] = v.x;
            As[kq + 1][row] = v.y;
            As[kq + 2][row] = v.z;
            As[kq + 3][row] = v.w;
        }
        {
            int kk = tid >> 5, col = (tid & 31) * 4;
            float4 v = *reinterpret_cast<const float4*>(&B[(k0 + kk)*F1 + bn + col]);
            *reinterpret_cast<float4*>(&Bs[kk][col]) = v;
        }
        __syncthreads();
        #pragma unroll
        for (int k = 0; k < TK; k++) {
            float a[8], b[8];
            #pragma unroll
            for (int i = 0; i < 8; i += 4)
                *reinterpret_cast<float4*>(&a[i]) = *reinterpret_cast<const float4*>(&As[k][ty*8 + i]);
            #pragma unroll
            for (int i = 0; i < 8; i += 4)
                *reinterpret_cast<float4*>(&b[i]) = *reinterpret_cast<const float4*>(&Bs[k][tx*8 + i]);
            #pragma unroll
            for (int i = 0; i < 8; i++)
                #pragma unroll
                for (int j = 0; j < 8; j++)
                    acc[i][j] += a[i] * b[j];
        }
        __syncthreads();
    }
    #pragma unroll
    for (int i = 0; i < 8; i++) {
        int gr = bm + ty*8 + i;
        if (gr < Nn) {
            *reinterpret_cast<float4*>(&g_hs1[gr*F1 + bn + tx*8 + 0]) =
                make_float4(acc[i][0], acc[i][1], acc[i][2], acc[i][3]);
            *reinterpret_cast<float4*>(&g_hs1[gr*F1 + bn + tx*8 + 4]) =
                make_float4(acc[i][4], acc[i][5], acc[i][6], acc[i][7]);
        }
    }
}

// ---------------- layer-1 alphas: warp per node ----------------
__global__ void alpha1_kernel(const float* __restrict__ x) {
    int warp = (blockIdx.x * blockDim.x + threadIdx.x) >> 5;
    if (warp >= Nn) return;
    int lane = threadIdx.x & 31;
    float xv0 = x[warp*DIN + lane];
    float xv1 = x[warp*DIN + 32 + lane];
    float xv2 = x[warp*DIN + 64 + lane];
    float xv3 = x[warp*DIN + 96 + lane];
    #pragma unroll
    for (int h = 0; h < HEADS; h++) {
        const float* ws = &g_Wsr1[h*DIN];
        const float* wd = &g_Wdr1[h*DIN];
        float s = xv0*ws[lane] + xv1*ws[32+lane] + xv2*ws[64+lane] + xv3*ws[96+lane];
        float d = xv0*wd[lane] + xv1*wd[32+lane] + xv2*wd[64+lane] + xv3*wd[96+lane];
        #pragma unroll
        for (int off = 16; off; off >>= 1) {
            s += __shfl_down_sync(0xffffffffu, s, off);
            d += __shfl_down_sync(0xffffffffu, d, off);
        }
        if (lane == 0) { g_as1[warp*HEADS + h] = s; g_ad1[warp*HEADS + h] = d; }
    }
}

// ---------------- layer-1 edge weights (CSR order, edge-parallel) ----------------
__global__ void weights1_kernel() {
    int j = blockIdx.x * blockDim.x + threadIdx.x;
    if (j >= Ee) return;
    int s = g_esrc[j], d = g_edst[j];
    float4 a0 = *reinterpret_cast<const float4*>(&g_as1[s*HEADS]);
    float4 a1 = *reinterpret_cast<const float4*>(&g_as1[s*HEADS + 4]);
    float4 b0 = *reinterpret_cast<const float4*>(&g_ad1[d*HEADS]);
    float4 b1 = *reinterpret_cast<const float4*>(&g_ad1[d*HEADS + 4]);
    float4 w0 = make_float4(__expf(leaky(a0.x + b0.x)), __expf(leaky(a0.y + b0.y)),
                            __expf(leaky(a0.z + b0.z)), __expf(leaky(a0.w + b0.w)));
    float4 w1 = make_float4(__expf(leaky(a1.x + b1.x)), __expf(leaky(a1.y + b1.y)),
                            __expf(leaky(a1.z + b1.z)), __expf(leaky(a1.w + b1.w)));
    *reinterpret_cast<float4*>(&g_w1[j*HEADS])     = w0;
    *reinterpret_cast<float4*>(&g_w1[j*HEADS + 4]) = w1;
}

// ---------------- layer-1 denominators: warp per node, read-only over w1 ----------------
__global__ void norm1_kernel() {
    int node = (blockIdx.x * blockDim.x + threadIdx.x) >> 5;
    if (node >= Nn) return;
    int lane = threadIdx.x & 31;
    int start = g_rowptr[node], end = g_rowptr[node + 1];
    int h = lane & 7;            // head
    int sub = lane >> 3;         // 0..3 edge-subslot
    float s = 0.f;
    for (int j = start + sub; j < end; j += 4)
        s += g_w1[j*HEADS + h];
    s += __shfl_xor_sync(0xffffffffu, s, 8);
    s += __shfl_xor_sync(0xffffffffu, s, 16);
    if (lane < 8) g_inv1[node*HEADS + lane] = 1.f / (s + 1e-16f);
}

// ---------------- layer-1 aggregate: warp per dst node, 4-edge unroll ----------------
__global__ void agg1_fused(const float* __restrict__ b1) {
    int node = (blockIdx.x * blockDim.x + threadIdx.x) >> 5;
    if (node >= Nn) return;
    int lane = threadIdx.x & 31;
    int wh = lane >> 2;           // head covering channels [lane*8, lane*8+8)
    int start = g_rowptr[node], end = g_rowptr[node + 1];

    float acc[8] = {};
    int j = start;
    for (; j + 4 <= end; j += 4) {
        int s0 = g_esrc[j], s1 = g_esrc[j+1], s2 = g_esrc[j+2], s3 = g_esrc[j+3];
        float w0 = g_w1[(j+0)*HEADS + wh];
        float w1 = g_w1[(j+1)*HEADS + wh];
        float w2 = g_w1[(j+2)*HEADS + wh];
        float w3 = g_w1[(j+3)*HEADS + wh];
        const float* r0 = &g_hs1[s0*F1 + lane*8];
        const float* r1 = &g_hs1[s1*F1 + lane*8];
        const float* r2 = &g_hs1[s2*F1 + lane*8];
        const float* r3 = &g_hs1[s3*F1 + lane*8];
        float4 p0 = *reinterpret_cast<const float4*>(r0);
        float4 p1 = *reinterpret_cast<const float4*>(r1);
        float4 p2 = *reinterpret_cast<const float4*>(r2);
        float4 p3 = *reinterpret_cast<const float4*>(r3);
        float4 q0 = *reinterpret_cast<const float4*>(r0 + 4);
        float4 q1 = *reinterpret_cast<const float4*>(r1 + 4);
        float4 q2 = *reinterpret_cast<const float4*>(r2 + 4);
        float4 q3 = *reinterpret_cast<const float4*>(r3 + 4);
        acc[0] += w0*p0.x + w1*p1.x + w2*p2.x + w3*p3.x;
        acc[1] += w0*p0.y + w1*p1.y + w2*p2.y + w3*p3.y;
        acc[2] += w0*p0.z + w1*p1.z + w2*p2.z + w3*p3.z;
        acc[3] += w0*p0.w + w1*p1.w + w2*p2.w + w3*p3.w;
        acc[4] += w0*q0.x + w1*q1.x + w2*q2.x + w3*q3.x;
        acc[5] += w0*q0.y + w1*q1.y + w2*q2.y + w3*q3.y;
        acc[6] += w0*q0.z + w1*q1.z + w2*q2.z + w3*q3.z;
        acc[7] += w0*q0.w + w1*q1.w + w2*q2.w + w3*q3.w;
    }
    for (; j < end; j++) {
        int s0 = g_esrc[j];
        float w0 = g_w1[j*HEADS + wh];
        const float* r0 = &g_hs1[s0*F1 + lane*8];
        float4 p0 = *reinterpret_cast<const float4*>(r0);
        float4 q0 = *reinterpret_cast<const float4*>(r0 + 4);
        acc[0] += w0*p0.x; acc[1] += w0*p0.y; acc[2] += w0*p0.z; acc[3] += w0*p0.w;
        acc[4] += w0*q0.x; acc[5] += w0*q0.y; acc[6] += w0*q0.z; acc[7] += w0*q0.w;
    }
    float inv = g_inv1[node*HEADS + wh];
    float4 bb0 = *reinterpret_cast<const float4*>(&b1[lane*8]);
    float4 bb1 = *reinterpret_cast<const float4*>(&b1[lane*8 + 4]);
    float* orow = &g_agg[node*F1 + lane*8];
    *reinterpret_cast<float4*>(orow) =
        make_float4(fmaxf(acc[0]*inv + bb0.x, 0.f), fmaxf(acc[1]*inv + bb0.y, 0.f),
                    fmaxf(acc[2]*inv + bb0.z, 0.f), fmaxf(acc[3]*inv + bb0.w, 0.f));
    *reinterpret_cast<float4*>(orow + 4) =
        make_float4(fmaxf(acc[4]*inv + bb1.x, 0.f), fmaxf(acc[5]*inv + bb1.y, 0.f),
                    fmaxf(acc[6]*inv + bb1.z, 0.f), fmaxf(acc[7]*inv + bb1.w, 0.f));
}

// ---------------- layer-2 GEMM + alphas: warp per node, W2 staged in smem ----------------
__global__ void gemm2_kernel(const float* __restrict__ W2s) {
    __shared__ float sW[F1*HID];
    __shared__ float sWsr[F1], sWdr[F1];
    for (int i = threadIdx.x; i < F1*HID; i += blockDim.x) sW[i] = W2s[i];
    for (int i = threadIdx.x; i < F1; i += blockDim.x) { sWsr[i] = g_Wsr2[i]; sWdr[i] = g_Wdr2[i]; }
    __syncthreads();
    int warp = threadIdx.x >> 5, lane = threadIdx.x & 31;
    int gw = blockIdx.x * (blockDim.x >> 5) + warp;
    int nwarps = gridDim.x * (blockDim.x >> 5);
    for (int n = gw; n < Nn; n += nwarps) {
        const float* hrow = &g_agg[n*F1];
        float acc = 0.f, als = 0.f, ald = 0.f;
        #pragma unroll
        for (int k0 = 0; k0 < F1; k0 += 32) {
            float hv = hrow[k0 + lane];
            als += hv * sWsr[k0 + lane];
            ald += hv * sWdr[k0 + lane];
            #pragma unroll
            for (int j = 0; j < 32; j++)
                acc += __shfl_sync(0xffffffffu, hv, j) * sW[(k0 + j)*HID + lane];
        }
        g_hs2[n*HID + lane] = acc;
        #pragma unroll
        for (int off = 16; off; off >>= 1) {
            als += __shfl_down_sync(0xffffffffu, als, off);
            ald += __shfl_down_sync(0xffffffffu, ald, off);
        }
        if (lane == 0) { g_as2[n] = als; g_ad2[n] = ald; }
    }
}

// ---------------- layer-2 edge weights + denominators ----------------
__global__ void weights2_kernel() {
    int j = blockIdx.x * blockDim.x + threadIdx.x;
    if (j >= Ee) return;
    g_w2[j] = __expf(leaky(g_as2[g_esrc[j]] + g_ad2[g_edst[j]]));
}

__global__ void norm2_kernel() {
    int node = (blockIdx.x * blockDim.x + threadIdx.x) >> 5;
    if (node >= Nn) return;
    int lane = threadIdx.x & 31;
    int start = g_rowptr[node], end = g_rowptr[node + 1];
    float s = 0.f;
    for (int j = start + lane; j < end; j += 32) s += g_w2[j];
    #pragma unroll
    for (int off = 16; off; off >>= 1) s += __shfl_xor_sync(0xffffffffu, s, off);
    if (lane == 0) g_inv2[node] = 1.f / (s + 1e-16f);
}

// ---------------- layer-2 aggregate: warp per dst node, 4-edge unroll ----------------
__global__ void agg2_fused(float* __restrict__ dout, const float* __restrict__ b2) {
    int node = (blockIdx.x * blockDim.x + threadIdx.x) >> 5;
    if (node >= Nn) return;
    int lane = threadIdx.x & 31;
    int start = g_rowptr[node], end = g_rowptr[node + 1];
    float acc = 0.f;
    int j = start;
    for (; j + 4 <= end; j += 4) {
        int s0 = g_esrc[j], s1 = g_esrc[j+1], s2 = g_esrc[j+2], s3 = g_esrc[j+3];
        float w0 = g_w2[j], w1 = g_w2[j+1], w2 = g_w2[j+2], w3 = g_w2[j+3];
        float v0 = g_hs2[s0*HID + lane];
        float v1 = g_hs2[s1*HID + lane];
        float v2 = g_hs2[s2*HID + lane];
        float v3 = g_hs2[s3*HID + lane];
        acc += w0*v0 + w1*v1 + w2*v2 + w3*v3;
    }
    for (; j < end; j++) acc += g_w2[j] * g_hs2[g_esrc[j]*HID + lane];
    dout[node*HID + lane] = acc * g_inv2[node] + b2[lane];
}

// ---------------- launch ----------------
extern "C" void kernel_launch(void* const* d_in, const int* in_sizes, int n_in,
                              void* d_out, int out_size) {
    const float* x   = (const float*)d_in[0];
    const int*   ei  = (const int*)d_in[1];
    const float* W1s = (const float*)d_in[2];
    const float* W1d = (const float*)d_in[3];
    const float* a1s = (const float*)d_in[4];
    const float* a1d = (const float*)d_in[5];
    const float* b1  = (const float*)d_in[6];
    const float* W2s = (const float*)d_in[7];
    const float* W2d = (const float*)d_in[8];
    const float* a2s = (const float*)d_in[9];
    const float* a2d = (const float*)d_in[10];
    const float* b2  = (const float*)d_in[11];
    float* dout = (float*)d_out;

    int eb   = (Ee + 255)/256;
    int nb32 = (Nn*32 + 255)/256;          // warp-per-node grids
    int sb   = (Nn + 1023)/1024;           // scan blocks (49)

    // launch order puts gemm1 at index 5 so ncu (-s 5 -c 1) profiles it
    init_kernel<<<(Nn + 255)/256, 256>>>();                                  // 0
    convert_idx<<<eb, 256>>>(ei);                                            // 1
    scan_blocks<<<sb, 1024>>>();                                             // 2
    scan_bsums<<<1, 64>>>(sb);                                               // 3
    scan_add<<<(Nn + 255)/256, 256>>>();                                     // 4
    dim3 g1(F1/128, (Nn + 127)/128);
    gemm1_kernel<<<g1, 256>>>(x, W1s);                                       // 5  <- profiled
    fill_kernel<<<eb, 256>>>();                                              // 6
    reduceW_kernel<<<6, 256>>>(W1s, W1d, a1s, a1d, W2s, W2d, a2s, a2d);      // 7
    alpha1_kernel<<<nb32, 256>>>(x);                                         // 8

    weights1_kernel<<<eb, 256>>>();
    norm1_kernel<<<nb32, 256>>>();
    agg1_fused<<<nb32, 256>>>(b1);

    gemm2_kernel<<<592, 256>>>(W2s);
    weights2_kernel<<<eb, 256>>>();
    norm2_kernel<<<nb32, 256>>>();
    agg2_fused<<<nb32, 256>>>(dout, b2);
}

// round 8
// speedup vs baseline: 1.0881x; 1.0881x over previous
#include <cuda_runtime.h>
#include <cuda_bf16.h>
#include <math_constants.h>

#define Nn 50000
#define Ee 800000
#define DIN 128
#define HID 32
#define HEADS 8
#define F1 (HEADS*HID)   // 256

// ---------------- scratch (static device globals; no allocation) ----------------
__device__ float g_hs1[Nn*F1];     // layer1 source features  [N,256]
__device__ float g_agg[Nn*F1];     // layer1 output h         [N,256]
__device__ float g_hs2[Nn*HID];    // layer2 source features  [N,32]
__device__ float g_as1[Nn*HEADS], g_ad1[Nn*HEADS];
__device__ float g_as2[Nn], g_ad2[Nn];
__device__ float g_inv1[Nn*HEADS];          // per-node per-head 1/denominator
__device__ float g_inv2[Nn];
__device__ float g_Wsr1[HEADS*DIN], g_Wdr1[HEADS*DIN];   // [h][k] layout
__device__ float g_Wsr2[F1], g_Wdr2[F1];
__device__ int   g_src[Ee], g_dst[Ee];     // decoded edge index (int32)
__device__ int   g_deg[Nn];                // in-degree histogram
__device__ int   g_rowptr[Nn + 1];         // CSR row pointers (by dst)
__device__ int   g_cursor[Nn];             // fill cursors
__device__ int   g_esrc[Ee];               // CSR column (src) ids
__device__ float g_w1[Ee*HEADS];           // per-edge per-head weights (CSR order, unnormalized)
__device__ float g_w2[Ee];                 // layer-2 per-edge weights (CSR order, unnormalized)
__device__ int   g_bsum[64];               // scan block sums

__device__ __forceinline__ float leaky(float v) { return v > 0.f ? v : 0.2f * v; }

// ---------------- init: zero degree histogram ----------------
__global__ void init_kernel() {
    int i = blockIdx.x * blockDim.x + threadIdx.x;
    if (i < Nn) g_deg[i] = 0;
}

// ---------------- edge index decode (int32 OR little-endian int64) + histogram ----------------
__global__ void convert_idx(const int* __restrict__ raw) {
    bool is_i64 = true;
    #pragma unroll
    for (int i = 0; i < 16; i++)
        if (raw[2*i + 1] != 0) is_i64 = false;
    int e = blockIdx.x * blockDim.x + threadIdx.x;
    if (e >= Ee) return;
    int s, d;
    if (is_i64) { s = raw[2*e]; d = raw[2*(Ee + e)]; }
    else        { s = raw[e];   d = raw[Ee + e]; }
    g_src[e] = s;
    g_dst[e] = d;
    atomicAdd(&g_deg[d], 1);
}

// ---------------- hierarchical scan ----------------
__global__ void scan_blocks() {
    __shared__ int sm[1024];
    int gid = blockIdx.x * 1024 + threadIdx.x;
    int v = (gid < Nn) ? g_deg[gid] : 0;
    sm[threadIdx.x] = v;
    __syncthreads();
    for (int off = 1; off < 1024; off <<= 1) {
        int t = (threadIdx.x >= off) ? sm[threadIdx.x - off] : 0;
        __syncthreads();
        sm[threadIdx.x] += t;
        __syncthreads();
    }
    if (gid < Nn) g_rowptr[gid] = sm[threadIdx.x] - v;
    if (threadIdx.x == 1023) g_bsum[blockIdx.x] = sm[1023];
}

__global__ void scan_bsums(int nblocks) {
    __shared__ int sm[64];
    int v = (threadIdx.x < nblocks) ? g_bsum[threadIdx.x] : 0;
    sm[threadIdx.x] = v;
    __syncthreads();
    for (int off = 1; off < 64; off <<= 1) {
        int t = (threadIdx.x >= off) ? sm[threadIdx.x - off] : 0;
        __syncthreads();
        sm[threadIdx.x] += t;
        __syncthreads();
    }
    if (threadIdx.x < nblocks) g_bsum[threadIdx.x] = sm[threadIdx.x] - v;
}

__global__ void scan_add() {
    int gid = blockIdx.x * blockDim.x + threadIdx.x;
    if (gid < Nn) {
        int r = g_rowptr[gid] + g_bsum[gid >> 10];
        g_rowptr[gid] = r;
        g_cursor[gid] = r;
    }
    if (gid == 0) g_rowptr[Nn] = Ee;
}

// ---------------- CSR fill ----------------
__global__ void fill_kernel() {
    int e = blockIdx.x * blockDim.x + threadIdx.x;
    if (e >= Ee) return;
    int pos = atomicAdd(&g_cursor[g_dst[e]], 1);
    g_esrc[pos] = g_src[e];
}

// ---------------- reduce attention weight vectors ----------------
__global__ void reduceW_kernel(const float* __restrict__ W1s, const float* __restrict__ W1d,
                               const float* __restrict__ a1s, const float* __restrict__ a1d,
                               const float* __restrict__ W2s, const float* __restrict__ W2d,
                               const float* __restrict__ a2s, const float* __restrict__ a2d) {
    int idx = blockIdx.x * blockDim.x + threadIdx.x;
    if (idx < HEADS*DIN) {
        int h = idx >> 7, k = idx & 127;
        float s = 0.f, d = 0.f;
        #pragma unroll
        for (int c = 0; c < HID; c++) {
            s += W1s[k*F1 + h*HID + c] * a1s[h*HID + c];
            d += W1d[k*F1 + h*HID + c] * a1d[h*HID + c];
        }
        g_Wsr1[h*DIN + k] = s;
        g_Wdr1[h*DIN + k] = d;
    } else if (idx < HEADS*DIN + F1) {
        int k = idx - HEADS*DIN;
        float s = 0.f, d = 0.f;
        #pragma unroll
        for (int c = 0; c < HID; c++) {
            s += W2s[k*HID + c] * a2s[c];
            d += W2d[k*HID + c] * a2d[c];
        }
        g_Wsr2[k] = s;
        g_Wdr2[k] = d;
    }
}

// ---------------- layer-1 GEMM: g_hs1 = x[N,128] @ W1_src[128,256] ----------------
__global__ void gemm1_kernel(const float* __restrict__ A, const float* __restrict__ B) {
    const int TK = 8;
    __shared__ float As[TK][132];
    __shared__ float Bs[TK][128];
    int bm = blockIdx.y * 128;
    int bn = blockIdx.x * 128;
    int tid = threadIdx.x;
    int tx = tid & 15;
    int ty = tid >> 4;
    float acc[8][8] = {};
    for (int k0 = 0; k0 < DIN; k0 += TK) {
        {
            int row = tid >> 1, kq = (tid & 1) * 4;
            int gr = bm + row;
            float4 v = make_float4(0.f, 0.f, 0.f, 0.f);
            if (gr < Nn) v = *reinterpret_cast<const float4*>(&A[gr*DIN + k0 + kq]);
            As[kq + 0][row] = v.x;
            As[kq + 1][row] = v.y;
            As[kq + 2][row] = v.z;
            As[kq + 3][row] = v.w;
        }
        {
            int kk = tid >> 5, col = (tid & 31) * 4;
            float4 v = *reinterpret_cast<const float4*>(&B[(k0 + kk)*F1 + bn + col]);
            *reinterpret_cast<float4*>(&Bs[kk][col]) = v;
        }
        __syncthreads();
        #pragma unroll
        for (int k = 0; k < TK; k++) {
            float a[8], b[8];
            #pragma unroll
            for (int i = 0; i < 8; i += 4)
                *reinterpret_cast<float4*>(&a[i]) = *reinterpret_cast<const float4*>(&As[k][ty*8 + i]);
            #pragma unroll
            for (int i = 0; i < 8; i += 4)
                *reinterpret_cast<float4*>(&b[i]) = *reinterpret_cast<const float4*>(&Bs[k][tx*8 + i]);
            #pragma unroll
            for (int i = 0; i < 8; i++)
                #pragma unroll
                for (int j = 0; j < 8; j++)
                    acc[i][j] += a[i] * b[j];
        }
        __syncthreads();
    }
    #pragma unroll
    for (int i = 0; i < 8; i++) {
        int gr = bm + ty*8 + i;
        if (gr < Nn) {
            *reinterpret_cast<float4*>(&g_hs1[gr*F1 + bn + tx*8 + 0]) =
                make_float4(acc[i][0], acc[i][1], acc[i][2], acc[i][3]);
            *reinterpret_cast<float4*>(&g_hs1[gr*F1 + bn + tx*8 + 4]) =
                make_float4(acc[i][4], acc[i][5], acc[i][6], acc[i][7]);
        }
    }
}

// ---------------- layer-1 alphas: warp per node ----------------
__global__ void alpha1_kernel(const float* __restrict__ x) {
    int warp = (blockIdx.x * blockDim.x + threadIdx.x) >> 5;
    if (warp >= Nn) return;
    int lane = threadIdx.x & 31;
    float xv0 = x[warp*DIN + lane];
    float xv1 = x[warp*DIN + 32 + lane];
    float xv2 = x[warp*DIN + 64 + lane];
    float xv3 = x[warp*DIN + 96 + lane];
    #pragma unroll
    for (int h = 0; h < HEADS; h++) {
        const float* ws = &g_Wsr1[h*DIN];
        const float* wd = &g_Wdr1[h*DIN];
        float s = xv0*ws[lane] + xv1*ws[32+lane] + xv2*ws[64+lane] + xv3*ws[96+lane];
        float d = xv0*wd[lane] + xv1*wd[32+lane] + xv2*wd[64+lane] + xv3*wd[96+lane];
        #pragma unroll
        for (int off = 16; off; off >>= 1) {
            s += __shfl_down_sync(0xffffffffu, s, off);
            d += __shfl_down_sync(0xffffffffu, d, off);
        }
        if (lane == 0) { g_as1[warp*HEADS + h] = s; g_ad1[warp*HEADS + h] = d; }
    }
}

// ---------------- layer-1 weights + denominators fused: warp per node ----------------
// lane = sub*8 + h: sub strides edges, h is the head. Computes w, stores it,
// reduces per-head sums in-warp, writes inv.
__global__ void w1norm1_kernel() {
    int node = (blockIdx.x * blockDim.x + threadIdx.x) >> 5;
    if (node >= Nn) return;
    int lane = threadIdx.x & 31;
    int h = lane & 7;
    int sub = lane >> 3;
    float adv = g_ad1[node*HEADS + h];
    int start = g_rowptr[node], end = g_rowptr[node + 1];
    float s = 0.f;
    for (int j = start + sub; j < end; j += 4) {
        int src = g_esrc[j];
        float w = __expf(leaky(g_as1[src*HEADS + h] + adv));
        g_w1[j*HEADS + h] = w;
        s += w;
    }
    s += __shfl_xor_sync(0xffffffffu, s, 8);
    s += __shfl_xor_sync(0xffffffffu, s, 16);
    if (lane < 8) g_inv1[node*HEADS + lane] = 1.f / (s + 1e-16f);
}

// ---------------- layer-1 aggregate: warp per dst node, 4-edge unroll ----------------
__global__ void agg1_fused(const float* __restrict__ b1) {
    int node = (blockIdx.x * blockDim.x + threadIdx.x) >> 5;
    if (node >= Nn) return;
    int lane = threadIdx.x & 31;
    int wh = lane >> 2;           // head covering channels [lane*8, lane*8+8)
    int start = g_rowptr[node], end = g_rowptr[node + 1];

    float acc[8] = {};
    int j = start;
    for (; j + 4 <= end; j += 4) {
        int s0 = g_esrc[j], s1 = g_esrc[j+1], s2 = g_esrc[j+2], s3 = g_esrc[j+3];
        float w0 = g_w1[(j+0)*HEADS + wh];
        float w1 = g_w1[(j+1)*HEADS + wh];
        float w2 = g_w1[(j+2)*HEADS + wh];
        float w3 = g_w1[(j+3)*HEADS + wh];
        const float* r0 = &g_hs1[s0*F1 + lane*8];
        const float* r1 = &g_hs1[s1*F1 + lane*8];
        const float* r2 = &g_hs1[s2*F1 + lane*8];
        const float* r3 = &g_hs1[s3*F1 + lane*8];
        float4 p0 = *reinterpret_cast<const float4*>(r0);
        float4 p1 = *reinterpret_cast<const float4*>(r1);
        float4 p2 = *reinterpret_cast<const float4*>(r2);
        float4 p3 = *reinterpret_cast<const float4*>(r3);
        float4 q0 = *reinterpret_cast<const float4*>(r0 + 4);
        float4 q1 = *reinterpret_cast<const float4*>(r1 + 4);
        float4 q2 = *reinterpret_cast<const float4*>(r2 + 4);
        float4 q3 = *reinterpret_cast<const float4*>(r3 + 4);
        acc[0] += w0*p0.x + w1*p1.x + w2*p2.x + w3*p3.x;
        acc[1] += w0*p0.y + w1*p1.y + w2*p2.y + w3*p3.y;
        acc[2] += w0*p0.z + w1*p1.z + w2*p2.z + w3*p3.z;
        acc[3] += w0*p0.w + w1*p1.w + w2*p2.w + w3*p3.w;
        acc[4] += w0*q0.x + w1*q1.x + w2*q2.x + w3*q3.x;
        acc[5] += w0*q0.y + w1*q1.y + w2*q2.y + w3*q3.y;
        acc[6] += w0*q0.z + w1*q1.z + w2*q2.z + w3*q3.z;
        acc[7] += w0*q0.w + w1*q1.w + w2*q2.w + w3*q3.w;
    }
    for (; j < end; j++) {
        int s0 = g_esrc[j];
        float w0 = g_w1[j*HEADS + wh];
        const float* r0 = &g_hs1[s0*F1 + lane*8];
        float4 p0 = *reinterpret_cast<const float4*>(r0);
        float4 q0 = *reinterpret_cast<const float4*>(r0 + 4);
        acc[0] += w0*p0.x; acc[1] += w0*p0.y; acc[2] += w0*p0.z; acc[3] += w0*p0.w;
        acc[4] += w0*q0.x; acc[5] += w0*q0.y; acc[6] += w0*q0.z; acc[7] += w0*q0.w;
    }
    float inv = g_inv1[node*HEADS + wh];
    float4 bb0 = *reinterpret_cast<const float4*>(&b1[lane*8]);
    float4 bb1 = *reinterpret_cast<const float4*>(&b1[lane*8 + 4]);
    float* orow = &g_agg[node*F1 + lane*8];
    *reinterpret_cast<float4*>(orow) =
        make_float4(fmaxf(acc[0]*inv + bb0.x, 0.f), fmaxf(acc[1]*inv + bb0.y, 0.f),
                    fmaxf(acc[2]*inv + bb0.z, 0.f), fmaxf(acc[3]*inv + bb0.w, 0.f));
    *reinterpret_cast<float4*>(orow + 4) =
        make_float4(fmaxf(acc[4]*inv + bb1.x, 0.f), fmaxf(acc[5]*inv + bb1.y, 0.f),
                    fmaxf(acc[6]*inv + bb1.z, 0.f), fmaxf(acc[7]*inv + bb1.w, 0.f));
}

// ---------------- layer-2 GEMM + alphas: warp per node, W2 staged in smem ----------------
__global__ void gemm2_kernel(const float* __restrict__ W2s) {
    __shared__ float sW[F1*HID];
    __shared__ float sWsr[F1], sWdr[F1];
    for (int i = threadIdx.x; i < F1*HID; i += blockDim.x) sW[i] = W2s[i];
    for (int i = threadIdx.x; i < F1; i += blockDim.x) { sWsr[i] = g_Wsr2[i]; sWdr[i] = g_Wdr2[i]; }
    __syncthreads();
    int warp = threadIdx.x >> 5, lane = threadIdx.x & 31;
    int gw = blockIdx.x * (blockDim.x >> 5) + warp;
    int nwarps = gridDim.x * (blockDim.x >> 5);
    for (int n = gw; n < Nn; n += nwarps) {
        const float* hrow = &g_agg[n*F1];
        float acc = 0.f, als = 0.f, ald = 0.f;
        #pragma unroll
        for (int k0 = 0; k0 < F1; k0 += 32) {
            float hv = hrow[k0 + lane];
            als += hv * sWsr[k0 + lane];
            ald += hv * sWdr[k0 + lane];
            #pragma unroll
            for (int j = 0; j < 32; j++)
                acc += __shfl_sync(0xffffffffu, hv, j) * sW[(k0 + j)*HID + lane];
        }
        g_hs2[n*HID + lane] = acc;
        #pragma unroll
        for (int off = 16; off; off >>= 1) {
            als += __shfl_down_sync(0xffffffffu, als, off);
            ald += __shfl_down_sync(0xffffffffu, ald, off);
        }
        if (lane == 0) { g_as2[n] = als; g_ad2[n] = ald; }
    }
}

// ---------------- layer-2 weights + denominators fused: warp per node ----------------
__global__ void w2norm2_kernel() {
    int node = (blockIdx.x * blockDim.x + threadIdx.x) >> 5;
    if (node >= Nn) return;
    int lane = threadIdx.x & 31;
    float adv = g_ad2[node];
    int start = g_rowptr[node], end = g_rowptr[node + 1];
    float s = 0.f;
    for (int j = start + lane; j < end; j += 32) {
        float w = __expf(leaky(g_as2[g_esrc[j]] + adv));
        g_w2[j] = w;
        s += w;
    }
    #pragma unroll
    for (int off = 16; off; off >>= 1) s += __shfl_xor_sync(0xffffffffu, s, off);
    if (lane == 0) g_inv2[node] = 1.f / (s + 1e-16f);
}

// ---------------- layer-2 aggregate: warp per dst node, 4-edge unroll ----------------
__global__ void agg2_fused(float* __restrict__ dout, const float* __restrict__ b2) {
    int node = (blockIdx.x * blockDim.x + threadIdx.x) >> 5;
    if (node >= Nn) return;
    int lane = threadIdx.x & 31;
    int start = g_rowptr[node], end = g_rowptr[node + 1];
    float acc = 0.f;
    int j = start;
    for (; j + 4 <= end; j += 4) {
        int s0 = g_esrc[j], s1 = g_esrc[j+1], s2 = g_esrc[j+2], s3 = g_esrc[j+3];
        float w0 = g_w2[j], w1 = g_w2[j+1], w2 = g_w2[j+2], w3 = g_w2[j+3];
        float v0 = g_hs2[s0*HID + lane];
        float v1 = g_hs2[s1*HID + lane];
        float v2 = g_hs2[s2*HID + lane];
        float v3 = g_hs2[s3*HID + lane];
        acc += w0*v0 + w1*v1 + w2*v2 + w3*v3;
    }
    for (; j < end; j++) acc += g_w2[j] * g_hs2[g_esrc[j]*HID + lane];
    dout[node*HID + lane] = acc * g_inv2[node] + b2[lane];
}

// ---------------- launch ----------------
extern "C" void kernel_launch(void* const* d_in, const int* in_sizes, int n_in,
                              void* d_out, int out_size) {
    const float* x   = (const float*)d_in[0];
    const int*   ei  = (const int*)d_in[1];
    const float* W1s = (const float*)d_in[2];
    const float* W1d = (const float*)d_in[3];
    const float* a1s = (const float*)d_in[4];
    const float* a1d = (const float*)d_in[5];
    const float* b1  = (const float*)d_in[6];
    const float* W2s = (const float*)d_in[7];
    const float* W2d = (const float*)d_in[8];
    const float* a2s = (const float*)d_in[9];
    const float* a2d = (const float*)d_in[10];
    const float* b2  = (const float*)d_in[11];
    float* dout = (float*)d_out;

    int eb   = (Ee + 255)/256;
    int nb32 = (Nn*32 + 255)/256;          // warp-per-node grids
    int sb   = (Nn + 1023)/1024;           // scan blocks (49)

    // Two-stream fork/join inside the capture: CSR build (stream 0) overlaps the
    // dense feature pipeline (sB). Created fresh per call (kernel_launch runs only
    // twice: correctness + capture), so no static state, deterministic work.
    cudaStream_t sB;
    cudaEvent_t e0, e1;
    cudaStreamCreateWithFlags(&sB, cudaStreamNonBlocking);
    cudaEventCreateWithFlags(&e0, cudaEventDisableTiming);
    cudaEventCreateWithFlags(&e1, cudaEventDisableTiming);

    cudaEventRecord(e0, 0);
    cudaStreamWaitEvent(sB, e0, 0);

    // stream B: dense pipeline
    reduceW_kernel<<<6, 256, 0, sB>>>(W1s, W1d, a1s, a1d, W2s, W2d, a2s, a2d);
    dim3 g1(F1/128, (Nn + 127)/128);
    gemm1_kernel<<<g1, 256, 0, sB>>>(x, W1s);
    alpha1_kernel<<<nb32, 256, 0, sB>>>(x);
    cudaEventRecord(e1, sB);

    // stream 0: CSR build
    init_kernel<<<(Nn + 255)/256, 256>>>();
    convert_idx<<<eb, 256>>>(ei);
    scan_blocks<<<sb, 1024>>>();
    scan_bsums<<<1, 64>>>(sb);
    scan_add<<<(Nn + 255)/256, 256>>>();
    fill_kernel<<<eb, 256>>>();

    // join: everything below needs both pipelines
    cudaStreamWaitEvent(0, e1, 0);

    w1norm1_kernel<<<nb32, 256>>>();
    agg1_fused<<<nb32, 256>>>(b1);

    gemm2_kernel<<<592, 256>>>(W2s);
    w2norm2_kernel<<<nb32, 256>>>();
    agg2_fused<<<nb32, 256>>>(dout, b2);

    cudaStreamDestroy(sB);
    cudaEventDestroy(e0);
    cudaEventDestroy(e1);
}

// round 9
// speedup vs baseline: 1.2139x; 1.1156x over previous
#include <cuda_runtime.h>
#include <cuda_fp16.h>
#include <math_constants.h>

#define Nn 50000
#define Ee 800000
#define DIN 128
#define HID 32
#define HEADS 8
#define F1 (HEADS*HID)   // 256

// ---------------- scratch (static device globals; no allocation) ----------------
__device__ __half g_hs1h[Nn*F1];   // layer1 source features, fp16 [N,256]
__device__ float  g_agg[Nn*F1];    // layer1 output h (fp32)     [N,256]
__device__ __half g_hs2h[Nn*HID];  // layer2 source features, fp16 [N,32]
__device__ float g_as1[Nn*HEADS], g_ad1[Nn*HEADS];
__device__ float g_as2[Nn], g_ad2[Nn];
__device__ float g_inv1[Nn*HEADS];          // per-node per-head 1/denominator
__device__ float g_inv2[Nn];
__device__ float g_Wsr1[HEADS*DIN], g_Wdr1[HEADS*DIN];   // [h][k] layout
__device__ float g_Wsr2[F1], g_Wdr2[F1];
__device__ int   g_src[Ee], g_dst[Ee];     // decoded edge index (int32)
__device__ int   g_deg[Nn];                // in-degree histogram
__device__ int   g_rowptr[Nn + 1];         // CSR row pointers (by dst)
__device__ int   g_cursor[Nn];             // fill cursors
__device__ int   g_esrc[Ee];               // CSR column (src) ids
__device__ float g_w1[Ee*HEADS];           // per-edge per-head weights (CSR order, unnormalized)
__device__ float g_w2[Ee];                 // layer-2 per-edge weights (CSR order, unnormalized)
__device__ int   g_bsum[64];               // scan block sums

__device__ __forceinline__ float leaky(float v) { return v > 0.f ? v : 0.2f * v; }

// ---------------- init: zero degree histogram ----------------
__global__ void init_kernel() {
    int i = blockIdx.x * blockDim.x + threadIdx.x;
    if (i < Nn) g_deg[i] = 0;
}

// ---------------- edge index decode (int32 OR little-endian int64) + histogram ----------------
__global__ void convert_idx(const int* __restrict__ raw) {
    bool is_i64 = true;
    #pragma unroll
    for (int i = 0; i < 16; i++)
        if (raw[2*i + 1] != 0) is_i64 = false;
    int e = blockIdx.x * blockDim.x + threadIdx.x;
    if (e >= Ee) return;
    int s, d;
    if (is_i64) { s = raw[2*e]; d = raw[2*(Ee + e)]; }
    else        { s = raw[e];   d = raw[Ee + e]; }
    g_src[e] = s;
    g_dst[e] = d;
    atomicAdd(&g_deg[d], 1);
}

// ---------------- hierarchical scan ----------------
__global__ void scan_blocks() {
    __shared__ int sm[1024];
    int gid = blockIdx.x * 1024 + threadIdx.x;
    int v = (gid < Nn) ? g_deg[gid] : 0;
    sm[threadIdx.x] = v;
    __syncthreads();
    for (int off = 1; off < 1024; off <<= 1) {
        int t = (threadIdx.x >= off) ? sm[threadIdx.x - off] : 0;
        __syncthreads();
        sm[threadIdx.x] += t;
        __syncthreads();
    }
    if (gid < Nn) g_rowptr[gid] = sm[threadIdx.x] - v;
    if (threadIdx.x == 1023) g_bsum[blockIdx.x] = sm[1023];
}

__global__ void scan_bsums(int nblocks) {
    __shared__ int sm[64];
    int v = (threadIdx.x < nblocks) ? g_bsum[threadIdx.x] : 0;
    sm[threadIdx.x] = v;
    __syncthreads();
    for (int off = 1; off < 64; off <<= 1) {
        int t = (threadIdx.x >= off) ? sm[threadIdx.x - off] : 0;
        __syncthreads();
        sm[threadIdx.x] += t;
        __syncthreads();
    }
    if (threadIdx.x < nblocks) g_bsum[threadIdx.x] = sm[threadIdx.x] - v;
}

__global__ void scan_add() {
    int gid = blockIdx.x * blockDim.x + threadIdx.x;
    if (gid < Nn) {
        int r = g_rowptr[gid] + g_bsum[gid >> 10];
        g_rowptr[gid] = r;
        g_cursor[gid] = r;
    }
    if (gid == 0) g_rowptr[Nn] = Ee;
}

// ---------------- CSR fill ----------------
__global__ void fill_kernel() {
    int e = blockIdx.x * blockDim.x + threadIdx.x;
    if (e >= Ee) return;
    int pos = atomicAdd(&g_cursor[g_dst[e]], 1);
    g_esrc[pos] = g_src[e];
}

// ---------------- reduce attention weight vectors ----------------
__global__ void reduceW_kernel(const float* __restrict__ W1s, const float* __restrict__ W1d,
                               const float* __restrict__ a1s, const float* __restrict__ a1d,
                               const float* __restrict__ W2s, const float* __restrict__ W2d,
                               const float* __restrict__ a2s, const float* __restrict__ a2d) {
    int idx = blockIdx.x * blockDim.x + threadIdx.x;
    if (idx < HEADS*DIN) {
        int h = idx >> 7, k = idx & 127;
        float s = 0.f, d = 0.f;
        #pragma unroll
        for (int c = 0; c < HID; c++) {
            s += W1s[k*F1 + h*HID + c] * a1s[h*HID + c];
            d += W1d[k*F1 + h*HID + c] * a1d[h*HID + c];
        }
        g_Wsr1[h*DIN + k] = s;
        g_Wdr1[h*DIN + k] = d;
    } else if (idx < HEADS*DIN + F1) {
        int k = idx - HEADS*DIN;
        float s = 0.f, d = 0.f;
        #pragma unroll
        for (int c = 0; c < HID; c++) {
            s += W2s[k*HID + c] * a2s[c];
            d += W2d[k*HID + c] * a2d[c];
        }
        g_Wsr2[k] = s;
        g_Wdr2[k] = d;
    }
}

// ---------------- layer-1 GEMM: g_hs1h = fp16(x[N,128] @ W1_src[128,256]) ----------------
__global__ void gemm1_kernel(const float* __restrict__ A, const float* __restrict__ B) {
    const int TK = 8;
    __shared__ float As[TK][132];
    __shared__ float Bs[TK][128];
    int bm = blockIdx.y * 128;
    int bn = blockIdx.x * 128;
    int tid = threadIdx.x;
    int tx = tid & 15;
    int ty = tid >> 4;
    float acc[8][8] = {};
    for (int k0 = 0; k0 < DIN; k0 += TK) {
        {
            int row = tid >> 1, kq = (tid & 1) * 4;
            int gr = bm + row;
            float4 v = make_float4(0.f, 0.f, 0.f, 0.f);
            if (gr < Nn) v = *reinterpret_cast<const float4*>(&A[gr*DIN + k0 + kq]);
            As[kq + 0][row] = v.x;
            As[kq + 1][row] = v.y;
            As[kq + 2][row] = v.z;
            As[kq + 3][row] = v.w;
        }
        {
            int kk = tid >> 5, col = (tid & 31) * 4;
            float4 v = *reinterpret_cast<const float4*>(&B[(k0 + kk)*F1 + bn + col]);
            *reinterpret_cast<float4*>(&Bs[kk][col]) = v;
        }
        __syncthreads();
        #pragma unroll
        for (int k = 0; k < TK; k++) {
            float a[8], b[8];
            #pragma unroll
            for (int i = 0; i < 8; i += 4)
                *reinterpret_cast<float4*>(&a[i]) = *reinterpret_cast<const float4*>(&As[k][ty*8 + i]);
            #pragma unroll
            for (int i = 0; i < 8; i += 4)
                *reinterpret_cast<float4*>(&b[i]) = *reinterpret_cast<const float4*>(&Bs[k][tx*8 + i]);
            #pragma unroll
            for (int i = 0; i < 8; i++)
                #pragma unroll
                for (int j = 0; j < 8; j++)
                    acc[i][j] += a[i] * b[j];
        }
        __syncthreads();
    }
    #pragma unroll
    for (int i = 0; i < 8; i++) {
        int gr = bm + ty*8 + i;
        if (gr < Nn) {
            __half2 h[4];
            h[0] = __floats2half2_rn(acc[i][0], acc[i][1]);
            h[1] = __floats2half2_rn(acc[i][2], acc[i][3]);
            h[2] = __floats2half2_rn(acc[i][4], acc[i][5]);
            h[3] = __floats2half2_rn(acc[i][6], acc[i][7]);
            *reinterpret_cast<uint4*>(&g_hs1h[gr*F1 + bn + tx*8]) = *reinterpret_cast<uint4*>(h);
        }
    }
}

// ---------------- layer-1 alphas: warp per node ----------------
__global__ void alpha1_kernel(const float* __restrict__ x) {
    int warp = (blockIdx.x * blockDim.x + threadIdx.x) >> 5;
    if (warp >= Nn) return;
    int lane = threadIdx.x & 31;
    float xv0 = x[warp*DIN + lane];
    float xv1 = x[warp*DIN + 32 + lane];
    float xv2 = x[warp*DIN + 64 + lane];
    float xv3 = x[warp*DIN + 96 + lane];
    #pragma unroll
    for (int h = 0; h < HEADS; h++) {
        const float* ws = &g_Wsr1[h*DIN];
        const float* wd = &g_Wdr1[h*DIN];
        float s = xv0*ws[lane] + xv1*ws[32+lane] + xv2*ws[64+lane] + xv3*ws[96+lane];
        float d = xv0*wd[lane] + xv1*wd[32+lane] + xv2*wd[64+lane] + xv3*wd[96+lane];
        #pragma unroll
        for (int off = 16; off; off >>= 1) {
            s += __shfl_down_sync(0xffffffffu, s, off);
            d += __shfl_down_sync(0xffffffffu, d, off);
        }
        if (lane == 0) { g_as1[warp*HEADS + h] = s; g_ad1[warp*HEADS + h] = d; }
    }
}

// ---------------- layer-1 weights + denominators fused: warp per node ----------------
__global__ void w1norm1_kernel() {
    int node = (blockIdx.x * blockDim.x + threadIdx.x) >> 5;
    if (node >= Nn) return;
    int lane = threadIdx.x & 31;
    int h = lane & 7;
    int sub = lane >> 3;
    float adv = g_ad1[node*HEADS + h];
    int start = g_rowptr[node], end = g_rowptr[node + 1];
    float s = 0.f;
    for (int j = start + sub; j < end; j += 4) {
        int src = g_esrc[j];
        float w = __expf(leaky(g_as1[src*HEADS + h] + adv));
        g_w1[j*HEADS + h] = w;
        s += w;
    }
    s += __shfl_xor_sync(0xffffffffu, s, 8);
    s += __shfl_xor_sync(0xffffffffu, s, 16);
    if (lane < 8) g_inv1[node*HEADS + lane] = 1.f / (s + 1e-16f);
}

// ---------------- layer-1 aggregate: warp per dst node, fp16 gathers, 4-edge unroll ----------------
__device__ __forceinline__ void fma8h(float* acc, float w, uint4 u) {
    __half2 h0 = *reinterpret_cast<__half2*>(&u.x);
    __half2 h1 = *reinterpret_cast<__half2*>(&u.y);
    __half2 h2 = *reinterpret_cast<__half2*>(&u.z);
    __half2 h3 = *reinterpret_cast<__half2*>(&u.w);
    float2 f0 = __half22float2(h0);
    float2 f1 = __half22float2(h1);
    float2 f2 = __half22float2(h2);
    float2 f3 = __half22float2(h3);
    acc[0] += w*f0.x; acc[1] += w*f0.y;
    acc[2] += w*f1.x; acc[3] += w*f1.y;
    acc[4] += w*f2.x; acc[5] += w*f2.y;
    acc[6] += w*f3.x; acc[7] += w*f3.y;
}

__global__ void agg1_fused(const float* __restrict__ b1) {
    int node = (blockIdx.x * blockDim.x + threadIdx.x) >> 5;
    if (node >= Nn) return;
    int lane = threadIdx.x & 31;
    int wh = lane >> 2;           // head covering channels [lane*8, lane*8+8)
    int start = g_rowptr[node], end = g_rowptr[node + 1];

    float acc[8] = {};
    int j = start;
    for (; j + 4 <= end; j += 4) {
        int s0 = g_esrc[j], s1 = g_esrc[j+1], s2 = g_esrc[j+2], s3 = g_esrc[j+3];
        float w0 = g_w1[(j+0)*HEADS + wh];
        float w1 = g_w1[(j+1)*HEADS + wh];
        float w2 = g_w1[(j+2)*HEADS + wh];
        float w3 = g_w1[(j+3)*HEADS + wh];
        uint4 u0 = *reinterpret_cast<const uint4*>(&g_hs1h[s0*F1 + lane*8]);
        uint4 u1 = *reinterpret_cast<const uint4*>(&g_hs1h[s1*F1 + lane*8]);
        uint4 u2 = *reinterpret_cast<const uint4*>(&g_hs1h[s2*F1 + lane*8]);
        uint4 u3 = *reinterpret_cast<const uint4*>(&g_hs1h[s3*F1 + lane*8]);
        fma8h(acc, w0, u0);
        fma8h(acc, w1, u1);
        fma8h(acc, w2, u2);
        fma8h(acc, w3, u3);
    }
    for (; j < end; j++) {
        int s0 = g_esrc[j];
        float w0 = g_w1[j*HEADS + wh];
        uint4 u0 = *reinterpret_cast<const uint4*>(&g_hs1h[s0*F1 + lane*8]);
        fma8h(acc, w0, u0);
    }
    float inv = g_inv1[node*HEADS + wh];
    float4 bb0 = *reinterpret_cast<const float4*>(&b1[lane*8]);
    float4 bb1 = *reinterpret_cast<const float4*>(&b1[lane*8 + 4]);
    float* orow = &g_agg[node*F1 + lane*8];
    *reinterpret_cast<float4*>(orow) =
        make_float4(fmaxf(acc[0]*inv + bb0.x, 0.f), fmaxf(acc[1]*inv + bb0.y, 0.f),
                    fmaxf(acc[2]*inv + bb0.z, 0.f), fmaxf(acc[3]*inv + bb0.w, 0.f));
    *reinterpret_cast<float4*>(orow + 4) =
        make_float4(fmaxf(acc[4]*inv + bb1.x, 0.f), fmaxf(acc[5]*inv + bb1.y, 0.f),
                    fmaxf(acc[6]*inv + bb1.z, 0.f), fmaxf(acc[7]*inv + bb1.w, 0.f));
}

// ---------------- layer-2 GEMM + alphas: warp per node, W2 staged in smem ----------------
__global__ void gemm2_kernel(const float* __restrict__ W2s) {
    __shared__ float sW[F1*HID];
    __shared__ float sWsr[F1], sWdr[F1];
    for (int i = threadIdx.x; i < F1*HID; i += blockDim.x) sW[i] = W2s[i];
    for (int i = threadIdx.x; i < F1; i += blockDim.x) { sWsr[i] = g_Wsr2[i]; sWdr[i] = g_Wdr2[i]; }
    __syncthreads();
    int warp = threadIdx.x >> 5, lane = threadIdx.x & 31;
    int gw = blockIdx.x * (blockDim.x >> 5) + warp;
    int nwarps = gridDim.x * (blockDim.x >> 5);
    for (int n = gw; n < Nn; n += nwarps) {
        const float* hrow = &g_agg[n*F1];
        float acc = 0.f, als = 0.f, ald = 0.f;
        #pragma unroll
        for (int k0 = 0; k0 < F1; k0 += 32) {
            float hv = hrow[k0 + lane];
            als += hv * sWsr[k0 + lane];
            ald += hv * sWdr[k0 + lane];
            #pragma unroll
            for (int j = 0; j < 32; j++)
                acc += __shfl_sync(0xffffffffu, hv, j) * sW[(k0 + j)*HID + lane];
        }
        g_hs2h[n*HID + lane] = __float2half_rn(acc);
        #pragma unroll
        for (int off = 16; off; off >>= 1) {
            als += __shfl_down_sync(0xffffffffu, als, off);
            ald += __shfl_down_sync(0xffffffffu, ald, off);
        }
        if (lane == 0) { g_as2[n] = als; g_ad2[n] = ald; }
    }
}

// ---------------- layer-2 weights + denominators fused: warp per node ----------------
__global__ void w2norm2_kernel() {
    int node = (blockIdx.x * blockDim.x + threadIdx.x) >> 5;
    if (node >= Nn) return;
    int lane = threadIdx.x & 31;
    float adv = g_ad2[node];
    int start = g_rowptr[node], end = g_rowptr[node + 1];
    float s = 0.f;
    for (int j = start + lane; j < end; j += 32) {
        float w = __expf(leaky(g_as2[g_esrc[j]] + adv));
        g_w2[j] = w;
        s += w;
    }
    #pragma unroll
    for (int off = 16; off; off >>= 1) s += __shfl_xor_sync(0xffffffffu, s, off);
    if (lane == 0) g_inv2[node] = 1.f / (s + 1e-16f);
}

// ---------------- layer-2 aggregate: warp per dst node, fp16 gathers, 4-edge unroll ----------------
__global__ void agg2_fused(float* __restrict__ dout, const float* __restrict__ b2) {
    int node = (blockIdx.x * blockDim.x + threadIdx.x) >> 5;
    if (node >= Nn) return;
    int lane = threadIdx.x & 31;
    int start = g_rowptr[node], end = g_rowptr[node + 1];
    float acc = 0.f;
    int j = start;
    for (; j + 4 <= end; j += 4) {
        int s0 = g_esrc[j], s1 = g_esrc[j+1], s2 = g_esrc[j+2], s3 = g_esrc[j+3];
        float w0 = g_w2[j], w1 = g_w2[j+1], w2 = g_w2[j+2], w3 = g_w2[j+3];
        float v0 = __half2float(g_hs2h[s0*HID + lane]);
        float v1 = __half2float(g_hs2h[s1*HID + lane]);
        float v2 = __half2float(g_hs2h[s2*HID + lane]);
        float v3 = __half2float(g_hs2h[s3*HID + lane]);
        acc += w0*v0 + w1*v1 + w2*v2 + w3*v3;
    }
    for (; j < end; j++) acc += g_w2[j] * __half2float(g_hs2h[g_esrc[j]*HID + lane]);
    dout[node*HID + lane] = acc * g_inv2[node] + b2[lane];
}

// ---------------- launch ----------------
extern "C" void kernel_launch(void* const* d_in, const int* in_sizes, int n_in,
                              void* d_out, int out_size) {
    const float* x   = (const float*)d_in[0];
    const int*   ei  = (const int*)d_in[1];
    const float* W1s = (const float*)d_in[2];
    const float* W1d = (const float*)d_in[3];
    const float* a1s = (const float*)d_in[4];
    const float* a1d = (const float*)d_in[5];
    const float* b1  = (const float*)d_in[6];
    const float* W2s = (const float*)d_in[7];
    const float* W2d = (const float*)d_in[8];
    const float* a2s = (const float*)d_in[9];
    const float* a2d = (const float*)d_in[10];
    const float* b2  = (const float*)d_in[11];
    float* dout = (float*)d_out;

    int eb   = (Ee + 255)/256;
    int nb32 = (Nn*32 + 255)/256;          // warp-per-node grids
    int sb   = (Nn + 1023)/1024;           // scan blocks (49)

    // Two-stream fork/join inside the capture: CSR build (stream 0) overlaps the
    // dense feature pipeline (sB). Created fresh per call; deterministic work.
    cudaStream_t sB;
    cudaEvent_t e0, e1;
    cudaStreamCreateWithFlags(&sB, cudaStreamNonBlocking);
    cudaEventCreateWithFlags(&e0, cudaEventDisableTiming);
    cudaEventCreateWithFlags(&e1, cudaEventDisableTiming);

    cudaEventRecord(e0, 0);
    cudaStreamWaitEvent(sB, e0, 0);

    // stream B: dense pipeline
    reduceW_kernel<<<6, 256, 0, sB>>>(W1s, W1d, a1s, a1d, W2s, W2d, a2s, a2d);
    dim3 g1(F1/128, (Nn + 127)/128);
    gemm1_kernel<<<g1, 256, 0, sB>>>(x, W1s);
    alpha1_kernel<<<nb32, 256, 0, sB>>>(x);
    cudaEventRecord(e1, sB);

    // stream 0: CSR build
    init_kernel<<<(Nn + 255)/256, 256>>>();
    convert_idx<<<eb, 256>>>(ei);
    scan_blocks<<<sb, 1024>>>();
    scan_bsums<<<1, 64>>>(sb);
    scan_add<<<(Nn + 255)/256, 256>>>();
    fill_kernel<<<eb, 256>>>();

    // join
    cudaStreamWaitEvent(0, e1, 0);

    w1norm1_kernel<<<nb32, 256>>>();
    agg1_fused<<<nb32, 256>>>(b1);

    gemm2_kernel<<<592, 256>>>(W2s);
    w2norm2_kernel<<<nb32, 256>>>();
    agg2_fused<<<nb32, 256>>>(dout, b2);

    cudaStreamDestroy(sB);
    cudaEventDestroy(e0);
    cudaEventDestroy(e1);
}

// round 10
// speedup vs baseline: 1.4766x; 1.2164x over previous
#include <cuda_runtime.h>
#include <cuda_fp16.h>
#include <math_constants.h>
#include <mma.h>

using namespace nvcuda;

#define Nn 50000
#define Ee 800000
#define DIN 128
#define HID 32
#define HEADS 8
#define F1 (HEADS*HID)   // 256

// ---------------- scratch (static device globals; no allocation) ----------------
__device__ __half g_xh[Nn*DIN];    // fp16 copy of x
__device__ __half g_W1h[DIN*F1];   // fp16 copy of W1_src
__device__ __half g_hs1h[Nn*F1];   // layer1 source features, fp16 [N,256]
__device__ float  g_agg[Nn*F1];    // layer1 output h (fp32)     [N,256]
__device__ __half g_hs2h[Nn*HID];  // layer2 source features, fp16 [N,32]
__device__ float g_as1[Nn*HEADS], g_ad1[Nn*HEADS];
__device__ float g_as2[Nn], g_ad2[Nn];
__device__ float g_Wsr1[HEADS*DIN], g_Wdr1[HEADS*DIN];   // [h][k] layout
__device__ float g_Wsr2[F1], g_Wdr2[F1];
__device__ int   g_src[Ee], g_dst[Ee];     // decoded edge index (int32)
__device__ int   g_deg[Nn];                // in-degree histogram
__device__ int   g_rowptr[Nn + 1];         // CSR row pointers (by dst)
__device__ int   g_cursor[Nn];             // fill cursors
__device__ int   g_esrc[Ee];               // CSR column (src) ids
__device__ int   g_bsum[64];               // scan block sums

__device__ __forceinline__ float leaky(float v) { return v > 0.f ? v : 0.2f * v; }

__device__ __forceinline__ uint2 pack4h(float4 v) {
    __half2 h0 = __floats2half2_rn(v.x, v.y);
    __half2 h1 = __floats2half2_rn(v.z, v.w);
    uint2 r;
    r.x = *reinterpret_cast<unsigned*>(&h0);
    r.y = *reinterpret_cast<unsigned*>(&h1);
    return r;
}

// ---------------- init: zero degree histogram ----------------
__global__ void init_kernel() {
    int i = blockIdx.x * blockDim.x + threadIdx.x;
    if (i < Nn) g_deg[i] = 0;
}

// ---------------- edge index decode (int32 OR little-endian int64) + histogram ----------------
__global__ void convert_idx(const int* __restrict__ raw) {
    bool is_i64 = true;
    #pragma unroll
    for (int i = 0; i < 16; i++)
        if (raw[2*i + 1] != 0) is_i64 = false;
    int e = blockIdx.x * blockDim.x + threadIdx.x;
    if (e >= Ee) return;
    int s, d;
    if (is_i64) { s = raw[2*e]; d = raw[2*(Ee + e)]; }
    else        { s = raw[e];   d = raw[Ee + e]; }
    g_src[e] = s;
    g_dst[e] = d;
    atomicAdd(&g_deg[d], 1);
}

// ---------------- hierarchical scan ----------------
__global__ void scan_blocks() {
    __shared__ int sm[1024];
    int gid = blockIdx.x * 1024 + threadIdx.x;
    int v = (gid < Nn) ? g_deg[gid] : 0;
    sm[threadIdx.x] = v;
    __syncthreads();
    for (int off = 1; off < 1024; off <<= 1) {
        int t = (threadIdx.x >= off) ? sm[threadIdx.x - off] : 0;
        __syncthreads();
        sm[threadIdx.x] += t;
        __syncthreads();
    }
    if (gid < Nn) g_rowptr[gid] = sm[threadIdx.x] - v;
    if (threadIdx.x == 1023) g_bsum[blockIdx.x] = sm[1023];
}

__global__ void scan_bsums(int nblocks) {
    __shared__ int sm[64];
    int v = (threadIdx.x < nblocks) ? g_bsum[threadIdx.x] : 0;
    sm[threadIdx.x] = v;
    __syncthreads();
    for (int off = 1; off < 64; off <<= 1) {
        int t = (threadIdx.x >= off) ? sm[threadIdx.x - off] : 0;
        __syncthreads();
        sm[threadIdx.x] += t;
        __syncthreads();
    }
    if (threadIdx.x < nblocks) g_bsum[threadIdx.x] = sm[threadIdx.x] - v;
}

__global__ void scan_add() {
    int gid = blockIdx.x * blockDim.x + threadIdx.x;
    if (gid < Nn) {
        int r = g_rowptr[gid] + g_bsum[gid >> 10];
        g_rowptr[gid] = r;
        g_cursor[gid] = r;
    }
    if (gid == 0) g_rowptr[Nn] = Ee;
}

// ---------------- CSR fill ----------------
__global__ void fill_kernel() {
    int e = blockIdx.x * blockDim.x + threadIdx.x;
    if (e >= Ee) return;
    int pos = atomicAdd(&g_cursor[g_dst[e]], 1);
    g_esrc[pos] = g_src[e];
}

// ---------------- fp16 conversions ----------------
__global__ void cvt_x_kernel(const float* __restrict__ x) {
    int i = blockIdx.x * blockDim.x + threadIdx.x;
    if (i < Nn*DIN/4) {
        float4 v = reinterpret_cast<const float4*>(x)[i];
        reinterpret_cast<uint2*>(g_xh)[i] = pack4h(v);
    }
}

__global__ void cvt_w_kernel(const float* __restrict__ W1s) {
    int i = blockIdx.x * blockDim.x + threadIdx.x;
    if (i < DIN*F1/4) {
        float4 v = reinterpret_cast<const float4*>(W1s)[i];
        reinterpret_cast<uint2*>(g_W1h)[i] = pack4h(v);
    }
}

// ---------------- reduce attention weight vectors ----------------
__global__ void reduceW_kernel(const float* __restrict__ W1s, const float* __restrict__ W1d,
                               const float* __restrict__ a1s, const float* __restrict__ a1d,
                               const float* __restrict__ W2s, const float* __restrict__ W2d,
                               const float* __restrict__ a2s, const float* __restrict__ a2d) {
    int idx = blockIdx.x * blockDim.x + threadIdx.x;
    if (idx < HEADS*DIN) {
        int h = idx >> 7, k = idx & 127;
        float s = 0.f, d = 0.f;
        #pragma unroll
        for (int c = 0; c < HID; c++) {
            s += W1s[k*F1 + h*HID + c] * a1s[h*HID + c];
            d += W1d[k*F1 + h*HID + c] * a1d[h*HID + c];
        }
        g_Wsr1[h*DIN + k] = s;
        g_Wdr1[h*DIN + k] = d;
    } else if (idx < HEADS*DIN + F1) {
        int k = idx - HEADS*DIN;
        float s = 0.f, d = 0.f;
        #pragma unroll
        for (int c = 0; c < HID; c++) {
            s += W2s[k*HID + c] * a2s[c];
            d += W2d[k*HID + c] * a2d[c];
        }
        g_Wsr2[k] = s;
        g_Wdr2[k] = d;
    }
}

// ---------------- layer-1 GEMM via WMMA tensor cores ----------------
// block tile 128(M) x 64(N), 8 warps in 4x2, each warp 32x32 (2x2 m16n16k16 frags)
__global__ void gemm1_wmma() {
    __shared__ __half As[128][24];       // A tile, padded
    __shared__ __half Bs[16][72];        // B tile, padded
    __shared__ float  Cst[8][16][20];    // per-warp epilogue staging
    int tid = threadIdx.x;
    int warp = tid >> 5, lane = tid & 31;
    int bm = blockIdx.y * 128, bn = blockIdx.x * 64;
    int wm = warp >> 1, wn = warp & 1;

    wmma::fragment<wmma::accumulator, 16, 16, 16, float> c[2][2];
    #pragma unroll
    for (int i = 0; i < 2; i++)
        #pragma unroll
        for (int j = 0; j < 2; j++)
            wmma::fill_fragment(c[i][j], 0.f);

    for (int k0 = 0; k0 < DIN; k0 += 16) {
        // A: 128 rows x 16 cols. thread: row=tid/2, col=(tid&1)*8 (uint4 = 8 halfs)
        {
            int ar = tid >> 1, ac = (tid & 1) * 8;
            int gr = bm + ar;
            uint4 v = make_uint4(0u, 0u, 0u, 0u);
            if (gr < Nn) v = *reinterpret_cast<const uint4*>(&g_xh[gr*DIN + k0 + ac]);
            *reinterpret_cast<uint4*>(&As[ar][ac]) = v;
        }
        // B: 16 rows x 64 cols. thread: row=tid/16, col=(tid&15)*4 (uint2 = 4 halfs)
        {
            int br = tid >> 4, bc = (tid & 15) * 4;
            *reinterpret_cast<uint2*>(&Bs[br][bc]) =
                *reinterpret_cast<const uint2*>(&g_W1h[(k0 + br)*F1 + bn + bc]);
        }
        __syncthreads();
        wmma::fragment<wmma::matrix_a, 16, 16, 16, __half, wmma::row_major> a[2];
        wmma::fragment<wmma::matrix_b, 16, 16, 16, __half, wmma::row_major> b[2];
        #pragma unroll
        for (int i = 0; i < 2; i++)
            wmma::load_matrix_sync(a[i], &As[wm*32 + i*16][0], 24);
        #pragma unroll
        for (int j = 0; j < 2; j++)
            wmma::load_matrix_sync(b[j], &Bs[0][wn*32 + j*16], 72);
        #pragma unroll
        for (int i = 0; i < 2; i++)
            #pragma unroll
            for (int j = 0; j < 2; j++)
                wmma::mma_sync(c[i][j], a[i], b[j], c[i][j]);
        __syncthreads();
    }

    // epilogue: stage each 16x16 float frag in smem, convert to half, write
    #pragma unroll
    for (int i = 0; i < 2; i++)
        #pragma unroll
        for (int j = 0; j < 2; j++) {
            wmma::store_matrix_sync(&Cst[warp][0][0], c[i][j], 20, wmma::mem_row_major);
            __syncwarp();
            int r = lane >> 1, cc = (lane & 1) * 8;
            int gr = bm + wm*32 + i*16 + r;
            if (gr < Nn) {
                float* p = &Cst[warp][r][cc];
                __half2 h[4];
                h[0] = __floats2half2_rn(p[0], p[1]);
                h[1] = __floats2half2_rn(p[2], p[3]);
                h[2] = __floats2half2_rn(p[4], p[5]);
                h[3] = __floats2half2_rn(p[6], p[7]);
                *reinterpret_cast<uint4*>(&g_hs1h[gr*F1 + bn + wn*32 + j*16 + cc]) =
                    *reinterpret_cast<uint4*>(h);
            }
            __syncwarp();
        }
}

// ---------------- layer-1 alphas: warp per node (fp32 x) ----------------
__global__ void alpha1_kernel(const float* __restrict__ x) {
    int warp = (blockIdx.x * blockDim.x + threadIdx.x) >> 5;
    if (warp >= Nn) return;
    int lane = threadIdx.x & 31;
    float xv0 = x[warp*DIN + lane];
    float xv1 = x[warp*DIN + 32 + lane];
    float xv2 = x[warp*DIN + 64 + lane];
    float xv3 = x[warp*DIN + 96 + lane];
    #pragma unroll
    for (int h = 0; h < HEADS; h++) {
        const float* ws = &g_Wsr1[h*DIN];
        const float* wd = &g_Wdr1[h*DIN];
        float s = xv0*ws[lane] + xv1*ws[32+lane] + xv2*ws[64+lane] + xv3*ws[96+lane];
        float d = xv0*wd[lane] + xv1*wd[32+lane] + xv2*wd[64+lane] + xv3*wd[96+lane];
        #pragma unroll
        for (int off = 16; off; off >>= 1) {
            s += __shfl_down_sync(0xffffffffu, s, off);
            d += __shfl_down_sync(0xffffffffu, d, off);
        }
        if (lane == 0) { g_as1[warp*HEADS + h] = s; g_ad1[warp*HEADS + h] = d; }
    }
}

// ---------------- layer-1 aggregate with inline softmax: warp per dst node ----------------
// lane's head wh = lane>>2 covers channels [lane*8, lane*8+8). Each lane computes
// the edge weight for its own head from the 32B as1 sector (no shfl), accumulates
// unnormalized weighted sum + weight sum; epilogue normalizes + bias + relu.
__device__ __forceinline__ void fma8h(float* acc, float w, uint4 u) {
    __half2 h0 = *reinterpret_cast<__half2*>(&u.x);
    __half2 h1 = *reinterpret_cast<__half2*>(&u.y);
    __half2 h2 = *reinterpret_cast<__half2*>(&u.z);
    __half2 h3 = *reinterpret_cast<__half2*>(&u.w);
    float2 f0 = __half22float2(h0);
    float2 f1 = __half22float2(h1);
    float2 f2 = __half22float2(h2);
    float2 f3 = __half22float2(h3);
    acc[0] += w*f0.x; acc[1] += w*f0.y;
    acc[2] += w*f1.x; acc[3] += w*f1.y;
    acc[4] += w*f2.x; acc[5] += w*f2.y;
    acc[6] += w*f3.x; acc[7] += w*f3.y;
}

__global__ void agg1_fused(const float* __restrict__ b1) {
    int node = (blockIdx.x * blockDim.x + threadIdx.x) >> 5;
    if (node >= Nn) return;
    int lane = threadIdx.x & 31;
    int wh = lane >> 2;
    float adv = g_ad1[node*HEADS + wh];
    int start = g_rowptr[node], end = g_rowptr[node + 1];

    float acc[8] = {};
    float wsum = 0.f;
    int j = start;
    for (; j + 2 <= end; j += 2) {
        int s0 = g_esrc[j], s1 = g_esrc[j+1];
        float w0 = __expf(leaky(g_as1[s0*HEADS + wh] + adv));
        float w1 = __expf(leaky(g_as1[s1*HEADS + wh] + adv));
        uint4 u0 = *reinterpret_cast<const uint4*>(&g_hs1h[s0*F1 + lane*8]);
        uint4 u1 = *reinterpret_cast<const uint4*>(&g_hs1h[s1*F1 + lane*8]);
        wsum += w0 + w1;
        fma8h(acc, w0, u0);
        fma8h(acc, w1, u1);
    }
    if (j < end) {
        int s0 = g_esrc[j];
        float w0 = __expf(leaky(g_as1[s0*HEADS + wh] + adv));
        uint4 u0 = *reinterpret_cast<const uint4*>(&g_hs1h[s0*F1 + lane*8]);
        wsum += w0;
        fma8h(acc, w0, u0);
    }
    float inv = 1.f / (wsum + 1e-16f);
    float4 bb0 = *reinterpret_cast<const float4*>(&b1[lane*8]);
    float4 bb1 = *reinterpret_cast<const float4*>(&b1[lane*8 + 4]);
    float* orow = &g_agg[node*F1 + lane*8];
    *reinterpret_cast<float4*>(orow) =
        make_float4(fmaxf(acc[0]*inv + bb0.x, 0.f), fmaxf(acc[1]*inv + bb0.y, 0.f),
                    fmaxf(acc[2]*inv + bb0.z, 0.f), fmaxf(acc[3]*inv + bb0.w, 0.f));
    *reinterpret_cast<float4*>(orow + 4) =
        make_float4(fmaxf(acc[4]*inv + bb1.x, 0.f), fmaxf(acc[5]*inv + bb1.y, 0.f),
                    fmaxf(acc[6]*inv + bb1.z, 0.f), fmaxf(acc[7]*inv + bb1.w, 0.f));
}

// ---------------- layer-2 GEMM + alphas: warp per node, W2 staged in smem ----------------
__global__ void gemm2_kernel(const float* __restrict__ W2s) {
    __shared__ float sW[F1*HID];
    __shared__ float sWsr[F1], sWdr[F1];
    for (int i = threadIdx.x; i < F1*HID; i += blockDim.x) sW[i] = W2s[i];
    for (int i = threadIdx.x; i < F1; i += blockDim.x) { sWsr[i] = g_Wsr2[i]; sWdr[i] = g_Wdr2[i]; }
    __syncthreads();
    int warp = threadIdx.x >> 5, lane = threadIdx.x & 31;
    int gw = blockIdx.x * (blockDim.x >> 5) + warp;
    int nwarps = gridDim.x * (blockDim.x >> 5);
    for (int n = gw; n < Nn; n += nwarps) {
        const float* hrow = &g_agg[n*F1];
        float acc = 0.f, als = 0.f, ald = 0.f;
        #pragma unroll
        for (int k0 = 0; k0 < F1; k0 += 32) {
            float hv = hrow[k0 + lane];
            als += hv * sWsr[k0 + lane];
            ald += hv * sWdr[k0 + lane];
            #pragma unroll
            for (int j = 0; j < 32; j++)
                acc += __shfl_sync(0xffffffffu, hv, j) * sW[(k0 + j)*HID + lane];
        }
        g_hs2h[n*HID + lane] = __float2half_rn(acc);
        #pragma unroll
        for (int off = 16; off; off >>= 1) {
            als += __shfl_down_sync(0xffffffffu, als, off);
            ald += __shfl_down_sync(0xffffffffu, ald, off);
        }
        if (lane == 0) { g_as2[n] = als; g_ad2[n] = ald; }
    }
}

// ---------------- layer-2 aggregate with inline softmax: warp per dst node ----------------
__global__ void agg2_fused(float* __restrict__ dout, const float* __restrict__ b2) {
    int node = (blockIdx.x * blockDim.x + threadIdx.x) >> 5;
    if (node >= Nn) return;
    int lane = threadIdx.x & 31;
    float adv = g_ad2[node];
    int start = g_rowptr[node], end = g_rowptr[node + 1];
    float acc = 0.f, wsum = 0.f;
    int j = start;
    for (; j + 2 <= end; j += 2) {
        int s0 = g_esrc[j], s1 = g_esrc[j+1];
        float w0 = __expf(leaky(g_as2[s0] + adv));
        float w1 = __expf(leaky(g_as2[s1] + adv));
        float v0 = __half2float(g_hs2h[s0*HID + lane]);
        float v1 = __half2float(g_hs2h[s1*HID + lane]);
        wsum += w0 + w1;
        acc += w0*v0 + w1*v1;
    }
    if (j < end) {
        int s0 = g_esrc[j];
        float w0 = __expf(leaky(g_as2[s0] + adv));
        wsum += w0;
        acc += w0 * __half2float(g_hs2h[s0*HID + lane]);
    }
    dout[node*HID + lane] = acc / (wsum + 1e-16f) + b2[lane];
}

// ---------------- launch ----------------
extern "C" void kernel_launch(void* const* d_in, const int* in_sizes, int n_in,
                              void* d_out, int out_size) {
    const float* x   = (const float*)d_in[0];
    const int*   ei  = (const int*)d_in[1];
    const float* W1s = (const float*)d_in[2];
    const float* W1d = (const float*)d_in[3];
    const float* a1s = (const float*)d_in[4];
    const float* a1d = (const float*)d_in[5];
    const float* b1  = (const float*)d_in[6];
    const float* W2s = (const float*)d_in[7];
    const float* W2d = (const float*)d_in[8];
    const float* a2s = (const float*)d_in[9];
    const float* a2d = (const float*)d_in[10];
    const float* b2  = (const float*)d_in[11];
    float* dout = (float*)d_out;

    int eb   = (Ee + 255)/256;
    int nb32 = (Nn*32 + 255)/256;          // warp-per-node grids
    int sb   = (Nn + 1023)/1024;           // scan blocks (49)

    cudaStream_t sB;
    cudaEvent_t e0, e1;
    cudaStreamCreateWithFlags(&sB, cudaStreamNonBlocking);
    cudaEventCreateWithFlags(&e0, cudaEventDisableTiming);
    cudaEventCreateWithFlags(&e1, cudaEventDisableTiming);

    cudaEventRecord(e0, 0);
    cudaStreamWaitEvent(sB, e0, 0);

    // stream B: dense pipeline (fp16 conversions -> tensor-core GEMM -> alphas)
    cvt_x_kernel<<<(Nn*DIN/4 + 255)/256, 256, 0, sB>>>(x);
    cvt_w_kernel<<<(DIN*F1/4 + 255)/256, 256, 0, sB>>>(W1s);
    reduceW_kernel<<<6, 256, 0, sB>>>(W1s, W1d, a1s, a1d, W2s, W2d, a2s, a2d);
    dim3 g1(F1/64, (Nn + 127)/128);
    gemm1_wmma<<<g1, 256, 0, sB>>>();
    alpha1_kernel<<<nb32, 256, 0, sB>>>(x);
    cudaEventRecord(e1, sB);

    // stream 0: CSR build
    init_kernel<<<(Nn + 255)/256, 256>>>();
    convert_idx<<<eb, 256>>>(ei);
    scan_blocks<<<sb, 1024>>>();
    scan_bsums<<<1, 64>>>(sb);
    scan_add<<<(Nn + 255)/256, 256>>>();
    fill_kernel<<<eb, 256>>>();

    // join
    cudaStreamWaitEvent(0, e1, 0);

    agg1_fused<<<nb32, 256>>>(b1);
    gemm2_kernel<<<592, 256>>>(W2s);
    agg2_fused<<<nb32, 256>>>(dout, b2);

    cudaStreamDestroy(sB);
    cudaEventDestroy(e0);
    cudaEventDestroy(e1);
}

// round 11
// speedup vs baseline: 2.2268x; 1.5081x over previous
#include <cuda_runtime.h>
#include <cuda_fp16.h>
#include <math_constants.h>
#include <mma.h>

using namespace nvcuda;

#define Nn 50000
#define Ee 800000
#define DIN 128
#define HID 32
#define HEADS 8
#define F1 (HEADS*HID)   // 256
#define NPAD 50048       // Nn rounded up to 128 (WMMA M-tile)

// ---------------- scratch (static device globals; no allocation) ----------------
__device__ __half g_hs1h[NPAD*F1];   // layer1 source features, fp16 [N,256]
__device__ __half g_aggh[NPAD*F1];   // layer1 output h, fp16 [N,256] (padded for WMMA)
__device__ __half g_hs2h[NPAD*HID];  // layer2 source features, fp16 [N,32]
__device__ float g_as1[Nn*HEADS], g_ad1[Nn*HEADS];
__device__ float g_as2[Nn], g_ad2[Nn];
__device__ float g_Wsr1[HEADS*DIN], g_Wdr1[HEADS*DIN];   // [h][k] layout
__device__ float g_Wsr2[F1], g_Wdr2[F1];
__device__ int   g_src[Ee], g_dst[Ee];     // decoded edge index (int32)
__device__ int   g_deg[Nn];                // in-degree histogram
__device__ int   g_rowptr[Nn + 1];         // CSR row pointers (by dst)
__device__ int   g_cursor[Nn];             // fill cursors
__device__ int   g_esrc[Ee];               // CSR column (src) ids
__device__ int   g_bsum[64];               // scan block sums

__device__ __forceinline__ float leaky(float v) { return v > 0.f ? v : 0.2f * v; }

__device__ __forceinline__ uint2 pack4h(float4 v) {
    __half2 h0 = __floats2half2_rn(v.x, v.y);
    __half2 h1 = __floats2half2_rn(v.z, v.w);
    uint2 r;
    r.x = *reinterpret_cast<unsigned*>(&h0);
    r.y = *reinterpret_cast<unsigned*>(&h1);
    return r;
}

// ---------------- init: zero degree histogram ----------------
__global__ void init_kernel() {
    int i = blockIdx.x * blockDim.x + threadIdx.x;
    if (i < Nn) g_deg[i] = 0;
}

// ---------------- edge index decode (int32 OR little-endian int64) + histogram ----------------
__global__ void convert_idx(const int* __restrict__ raw) {
    bool is_i64 = true;
    #pragma unroll
    for (int i = 0; i < 16; i++)
        if (raw[2*i + 1] != 0) is_i64 = false;
    int e = blockIdx.x * blockDim.x + threadIdx.x;
    if (e >= Ee) return;
    int s, d;
    if (is_i64) { s = raw[2*e]; d = raw[2*(Ee + e)]; }
    else        { s = raw[e];   d = raw[Ee + e]; }
    g_src[e] = s;
    g_dst[e] = d;
    atomicAdd(&g_deg[d], 1);
}

// ---------------- hierarchical scan ----------------
__global__ void scan_blocks() {
    __shared__ int sm[1024];
    int gid = blockIdx.x * 1024 + threadIdx.x;
    int v = (gid < Nn) ? g_deg[gid] : 0;
    sm[threadIdx.x] = v;
    __syncthreads();
    for (int off = 1; off < 1024; off <<= 1) {
        int t = (threadIdx.x >= off) ? sm[threadIdx.x - off] : 0;
        __syncthreads();
        sm[threadIdx.x] += t;
        __syncthreads();
    }
    if (gid < Nn) g_rowptr[gid] = sm[threadIdx.x] - v;
    if (threadIdx.x == 1023) g_bsum[blockIdx.x] = sm[1023];
}

__global__ void scan_bsums(int nblocks) {
    __shared__ int sm[64];
    int v = (threadIdx.x < nblocks) ? g_bsum[threadIdx.x] : 0;
    sm[threadIdx.x] = v;
    __syncthreads();
    for (int off = 1; off < 64; off <<= 1) {
        int t = (threadIdx.x >= off) ? sm[threadIdx.x - off] : 0;
        __syncthreads();
        sm[threadIdx.x] += t;
        __syncthreads();
    }
    if (threadIdx.x < nblocks) g_bsum[threadIdx.x] = sm[threadIdx.x] - v;
}

__global__ void scan_add() {
    int gid = blockIdx.x * blockDim.x + threadIdx.x;
    if (gid < Nn) {
        int r = g_rowptr[gid] + g_bsum[gid >> 10];
        g_rowptr[gid] = r;
        g_cursor[gid] = r;
    }
    if (gid == 0) g_rowptr[Nn] = Ee;
}

// ---------------- CSR fill ----------------
__global__ void fill_kernel() {
    int e = blockIdx.x * blockDim.x + threadIdx.x;
    if (e >= Ee) return;
    int pos = atomicAdd(&g_cursor[g_dst[e]], 1);
    g_esrc[pos] = g_src[e];
}

// ---------------- reduce attention weight vectors ----------------
__global__ void reduceW_kernel(const float* __restrict__ W1s, const float* __restrict__ W1d,
                               const float* __restrict__ a1s, const float* __restrict__ a1d,
                               const float* __restrict__ W2s, const float* __restrict__ W2d,
                               const float* __restrict__ a2s, const float* __restrict__ a2d) {
    int idx = blockIdx.x * blockDim.x + threadIdx.x;
    if (idx < HEADS*DIN) {
        int h = idx >> 7, k = idx & 127;
        float s = 0.f, d = 0.f;
        #pragma unroll
        for (int c = 0; c < HID; c++) {
            s += W1s[k*F1 + h*HID + c] * a1s[h*HID + c];
            d += W1d[k*F1 + h*HID + c] * a1d[h*HID + c];
        }
        g_Wsr1[h*DIN + k] = s;
        g_Wdr1[h*DIN + k] = d;
    } else if (idx < HEADS*DIN + F1) {
        int k = idx - HEADS*DIN;
        float s = 0.f, d = 0.f;
        #pragma unroll
        for (int c = 0; c < HID; c++) {
            s += W2s[k*HID + c] * a2s[c];
            d += W2d[k*HID + c] * a2d[c];
        }
        g_Wsr2[k] = s;
        g_Wdr2[k] = d;
    }
}

// ---------------- layer-1 GEMM via WMMA, K-tile 32, inline fp32->fp16 staging ----------------
// block tile 128(M) x 64(N), 8 warps 4x2, warp 32x32 (2x2 m16n16k16 frags)
__global__ void gemm1_wmma(const float* __restrict__ A, const float* __restrict__ B) {
    __shared__ __half As[128][40];       // 32 k + pad
    __shared__ __half Bs[32][72];        // 64 n + pad
    __shared__ float  Cst[8][16][20];
    int tid = threadIdx.x;
    int warp = tid >> 5, lane = tid & 31;
    int bm = blockIdx.y * 128, bn = blockIdx.x * 64;
    int wm = warp >> 1, wn = warp & 1;

    wmma::fragment<wmma::accumulator, 16, 16, 16, float> c[2][2];
    #pragma unroll
    for (int i = 0; i < 2; i++)
        #pragma unroll
        for (int j = 0; j < 2; j++)
            wmma::fill_fragment(c[i][j], 0.f);

    for (int k0 = 0; k0 < DIN; k0 += 32) {
        // A: 128 rows x 32 k, fp32 -> fp16. thread: row=tid/2, colgrp=(tid&1)*16
        {
            int ar = tid >> 1, ac = (tid & 1) * 16;
            int gr = bm + ar;
            #pragma unroll
            for (int q = 0; q < 4; q++) {
                float4 v = make_float4(0.f, 0.f, 0.f, 0.f);
                if (gr < Nn) v = *reinterpret_cast<const float4*>(&A[gr*DIN + k0 + ac + q*4]);
                *reinterpret_cast<uint2*>(&As[ar][ac + q*4]) = pack4h(v);
            }
        }
        // B: 32 rows x 64 n, fp32 -> fp16. thread: row=tid/8, colgrp=(tid&7)*8
        {
            int br = tid >> 3, bc = (tid & 7) * 8;
            #pragma unroll
            for (int q = 0; q < 2; q++) {
                float4 v = *reinterpret_cast<const float4*>(&B[(k0 + br)*F1 + bn + bc + q*4]);
                *reinterpret_cast<uint2*>(&Bs[br][bc + q*4]) = pack4h(v);
            }
        }
        __syncthreads();
        #pragma unroll
        for (int ks = 0; ks < 32; ks += 16) {
            wmma::fragment<wmma::matrix_a, 16, 16, 16, __half, wmma::row_major> a[2];
            wmma::fragment<wmma::matrix_b, 16, 16, 16, __half, wmma::row_major> b[2];
            #pragma unroll
            for (int i = 0; i < 2; i++)
                wmma::load_matrix_sync(a[i], &As[wm*32 + i*16][ks], 40);
            #pragma unroll
            for (int j = 0; j < 2; j++)
                wmma::load_matrix_sync(b[j], &Bs[ks][wn*32 + j*16], 72);
            #pragma unroll
            for (int i = 0; i < 2; i++)
                #pragma unroll
                for (int j = 0; j < 2; j++)
                    wmma::mma_sync(c[i][j], a[i], b[j], c[i][j]);
        }
        __syncthreads();
    }

    #pragma unroll
    for (int i = 0; i < 2; i++)
        #pragma unroll
        for (int j = 0; j < 2; j++) {
            wmma::store_matrix_sync(&Cst[warp][0][0], c[i][j], 20, wmma::mem_row_major);
            __syncwarp();
            int r = lane >> 1, cc = (lane & 1) * 8;
            int gr = bm + wm*32 + i*16 + r;
            if (gr < Nn) {
                float* p = &Cst[warp][r][cc];
                __half2 h[4];
                h[0] = __floats2half2_rn(p[0], p[1]);
                h[1] = __floats2half2_rn(p[2], p[3]);
                h[2] = __floats2half2_rn(p[4], p[5]);
                h[3] = __floats2half2_rn(p[6], p[7]);
                *reinterpret_cast<uint4*>(&g_hs1h[gr*F1 + bn + wn*32 + j*16 + cc]) =
                    *reinterpret_cast<uint4*>(h);
            }
            __syncwarp();
        }
}

// ---------------- layer-1 alphas: warp per node (fp32 x) ----------------
__global__ void alpha1_kernel(const float* __restrict__ x) {
    int warp = (blockIdx.x * blockDim.x + threadIdx.x) >> 5;
    if (warp >= Nn) return;
    int lane = threadIdx.x & 31;
    float xv0 = x[warp*DIN + lane];
    float xv1 = x[warp*DIN + 32 + lane];
    float xv2 = x[warp*DIN + 64 + lane];
    float xv3 = x[warp*DIN + 96 + lane];
    #pragma unroll
    for (int h = 0; h < HEADS; h++) {
        const float* ws = &g_Wsr1[h*DIN];
        const float* wd = &g_Wdr1[h*DIN];
        float s = xv0*ws[lane] + xv1*ws[32+lane] + xv2*ws[64+lane] + xv3*ws[96+lane];
        float d = xv0*wd[lane] + xv1*wd[32+lane] + xv2*wd[64+lane] + xv3*wd[96+lane];
        #pragma unroll
        for (int off = 16; off; off >>= 1) {
            s += __shfl_down_sync(0xffffffffu, s, off);
            d += __shfl_down_sync(0xffffffffu, d, off);
        }
        if (lane == 0) { g_as1[warp*HEADS + h] = s; g_ad1[warp*HEADS + h] = d; }
    }
}

// ---------------- layer-1 aggregate with inline softmax: warp per dst node ----------------
__device__ __forceinline__ void fma8h(float* acc, float w, uint4 u) {
    __half2 h0 = *reinterpret_cast<__half2*>(&u.x);
    __half2 h1 = *reinterpret_cast<__half2*>(&u.y);
    __half2 h2 = *reinterpret_cast<__half2*>(&u.z);
    __half2 h3 = *reinterpret_cast<__half2*>(&u.w);
    float2 f0 = __half22float2(h0);
    float2 f1 = __half22float2(h1);
    float2 f2 = __half22float2(h2);
    float2 f3 = __half22float2(h3);
    acc[0] += w*f0.x; acc[1] += w*f0.y;
    acc[2] += w*f1.x; acc[3] += w*f1.y;
    acc[4] += w*f2.x; acc[5] += w*f2.y;
    acc[6] += w*f3.x; acc[7] += w*f3.y;
}

__global__ void agg1_fused(const float* __restrict__ b1) {
    int node = (blockIdx.x * blockDim.x + threadIdx.x) >> 5;
    if (node >= Nn) return;
    int lane = threadIdx.x & 31;
    int wh = lane >> 2;
    float adv = g_ad1[node*HEADS + wh];
    int start = g_rowptr[node], end = g_rowptr[node + 1];

    float acc[8] = {};
    float wsum = 0.f;
    int j = start;
    for (; j + 2 <= end; j += 2) {
        int s0 = g_esrc[j], s1 = g_esrc[j+1];
        float w0 = __expf(leaky(g_as1[s0*HEADS + wh] + adv));
        float w1 = __expf(leaky(g_as1[s1*HEADS + wh] + adv));
        uint4 u0 = *reinterpret_cast<const uint4*>(&g_hs1h[s0*F1 + lane*8]);
        uint4 u1 = *reinterpret_cast<const uint4*>(&g_hs1h[s1*F1 + lane*8]);
        wsum += w0 + w1;
        fma8h(acc, w0, u0);
        fma8h(acc, w1, u1);
    }
    if (j < end) {
        int s0 = g_esrc[j];
        float w0 = __expf(leaky(g_as1[s0*HEADS + wh] + adv));
        uint4 u0 = *reinterpret_cast<const uint4*>(&g_hs1h[s0*F1 + lane*8]);
        wsum += w0;
        fma8h(acc, w0, u0);
    }
    float inv = 1.f / (wsum + 1e-16f);
    float4 bb0 = *reinterpret_cast<const float4*>(&b1[lane*8]);
    float4 bb1 = *reinterpret_cast<const float4*>(&b1[lane*8 + 4]);
    // h = relu(acc*inv + b), stored directly as fp16
    float4 o0 = make_float4(fmaxf(acc[0]*inv + bb0.x, 0.f), fmaxf(acc[1]*inv + bb0.y, 0.f),
                            fmaxf(acc[2]*inv + bb0.z, 0.f), fmaxf(acc[3]*inv + bb0.w, 0.f));
    float4 o1 = make_float4(fmaxf(acc[4]*inv + bb1.x, 0.f), fmaxf(acc[5]*inv + bb1.y, 0.f),
                            fmaxf(acc[6]*inv + bb1.z, 0.f), fmaxf(acc[7]*inv + bb1.w, 0.f));
    uint2 p0 = pack4h(o0), p1 = pack4h(o1);
    uint4 pk = make_uint4(p0.x, p0.y, p1.x, p1.y);
    *reinterpret_cast<uint4*>(&g_aggh[node*F1 + lane*8]) = pk;
}

// ---------------- layer-2 GEMM via WMMA: hs2 = h[N,256] @ W2_src[256,32] ----------------
// block: 128 M rows, 8 warps, each warp 16 rows x 32 cols (1x2 frags), k 16 steps.
// B (256x32 fp16) resident in smem; A frags loaded straight from g_aggh (padded).
__global__ void gemm2_wmma(const float* __restrict__ W2s) {
    __shared__ __half Bs[256][40];
    __shared__ float  Cst[8][16][36];
    int tid = threadIdx.x;
    int warp = tid >> 5, lane = tid & 31;
    int bm = blockIdx.x * 128;

    // stage B: thread tid loads row tid (32 floats -> 32 halfs)
    {
        int row = tid;
        #pragma unroll
        for (int q = 0; q < 8; q++) {
            float4 v = *reinterpret_cast<const float4*>(&W2s[row*HID + q*4]);
            *reinterpret_cast<uint2*>(&Bs[row][q*4]) = pack4h(v);
        }
    }
    __syncthreads();

    wmma::fragment<wmma::accumulator, 16, 16, 16, float> c[2];
    wmma::fill_fragment(c[0], 0.f);
    wmma::fill_fragment(c[1], 0.f);

    const __half* arow = &g_aggh[(bm + warp*16)*F1];
    #pragma unroll
    for (int k0 = 0; k0 < F1; k0 += 16) {
        wmma::fragment<wmma::matrix_a, 16, 16, 16, __half, wmma::row_major> a;
        wmma::load_matrix_sync(a, arow + k0, F1);
        wmma::fragment<wmma::matrix_b, 16, 16, 16, __half, wmma::row_major> b0, b1;
        wmma::load_matrix_sync(b0, &Bs[k0][0], 40);
        wmma::load_matrix_sync(b1, &Bs[k0][16], 40);
        wmma::mma_sync(c[0], a, b0, c[0]);
        wmma::mma_sync(c[1], a, b1, c[1]);
    }

    wmma::store_matrix_sync(&Cst[warp][0][0],  c[0], 36, wmma::mem_row_major);
    wmma::store_matrix_sync(&Cst[warp][0][16], c[1], 36, wmma::mem_row_major);
    __syncwarp();
    int r = lane >> 1, cc = (lane & 1) * 16;
    int gr = bm + warp*16 + r;
    if (gr < Nn) {
        float* p = &Cst[warp][r][cc];
        __half2 h[8];
        #pragma unroll
        for (int q = 0; q < 8; q++) h[q] = __floats2half2_rn(p[2*q], p[2*q+1]);
        *reinterpret_cast<uint4*>(&g_hs2h[gr*HID + cc])     = *reinterpret_cast<uint4*>(h);
        *reinterpret_cast<uint4*>(&g_hs2h[gr*HID + cc + 8]) = *reinterpret_cast<uint4*>(h + 4);
    }
}

// ---------------- layer-2 alphas: warp per node, fp16 h, fp32 weights/accum ----------------
__global__ void alpha2_kernel() {
    int node = (blockIdx.x * blockDim.x + threadIdx.x) >> 5;
    if (node >= Nn) return;
    int lane = threadIdx.x & 31;
    float s = 0.f, d = 0.f;
    #pragma unroll
    for (int c = 0; c < 8; c++) {
        float hv = __half2float(g_aggh[node*F1 + c*32 + lane]);
        s += hv * g_Wsr2[c*32 + lane];
        d += hv * g_Wdr2[c*32 + lane];
    }
    #pragma unroll
    for (int off = 16; off; off >>= 1) {
        s += __shfl_down_sync(0xffffffffu, s, off);
        d += __shfl_down_sync(0xffffffffu, d, off);
    }
    if (lane == 0) { g_as2[node] = s; g_ad2[node] = d; }
}

// ---------------- layer-2 aggregate with inline softmax: warp per dst node ----------------
__global__ void agg2_fused(float* __restrict__ dout, const float* __restrict__ b2) {
    int node = (blockIdx.x * blockDim.x + threadIdx.x) >> 5;
    if (node >= Nn) return;
    int lane = threadIdx.x & 31;
    float adv = g_ad2[node];
    int start = g_rowptr[node], end = g_rowptr[node + 1];
    float acc = 0.f, wsum = 0.f;
    int j = start;
    for (; j + 2 <= end; j += 2) {
        int s0 = g_esrc[j], s1 = g_esrc[j+1];
        float w0 = __expf(leaky(g_as2[s0] + adv));
        float w1 = __expf(leaky(g_as2[s1] + adv));
        float v0 = __half2float(g_hs2h[s0*HID + lane]);
        float v1 = __half2float(g_hs2h[s1*HID + lane]);
        wsum += w0 + w1;
        acc += w0*v0 + w1*v1;
    }
    if (j < end) {
        int s0 = g_esrc[j];
        float w0 = __expf(leaky(g_as2[s0] + adv));
        wsum += w0;
        acc += w0 * __half2float(g_hs2h[s0*HID + lane]);
    }
    dout[node*HID + lane] = acc / (wsum + 1e-16f) + b2[lane];
}

// ---------------- launch ----------------
extern "C" void kernel_launch(void* const* d_in, const int* in_sizes, int n_in,
                              void* d_out, int out_size) {
    const float* x   = (const float*)d_in[0];
    const int*   ei  = (const int*)d_in[1];
    const float* W1s = (const float*)d_in[2];
    const float* W1d = (const float*)d_in[3];
    const float* a1s = (const float*)d_in[4];
    const float* a1d = (const float*)d_in[5];
    const float* b1  = (const float*)d_in[6];
    const float* W2s = (const float*)d_in[7];
    const float* W2d = (const float*)d_in[8];
    const float* a2s = (const float*)d_in[9];
    const float* a2d = (const float*)d_in[10];
    const float* b2  = (const float*)d_in[11];
    float* dout = (float*)d_out;

    int eb   = (Ee + 255)/256;
    int nb32 = (Nn*32 + 255)/256;          // warp-per-node grids
    int sb   = (Nn + 1023)/1024;           // scan blocks (49)

    cudaStream_t sB;
    cudaEvent_t e0, e1;
    cudaStreamCreateWithFlags(&sB, cudaStreamNonBlocking);
    cudaEventCreateWithFlags(&e0, cudaEventDisableTiming);
    cudaEventCreateWithFlags(&e1, cudaEventDisableTiming);

    cudaEventRecord(e0, 0);
    cudaStreamWaitEvent(sB, e0, 0);

    // stream B: dense pipeline (tensor-core GEMM with inline conversion -> alphas)
    reduceW_kernel<<<6, 256, 0, sB>>>(W1s, W1d, a1s, a1d, W2s, W2d, a2s, a2d);
    dim3 g1(F1/64, (Nn + 127)/128);
    gemm1_wmma<<<g1, 256, 0, sB>>>(x, W1s);
    alpha1_kernel<<<nb32, 256, 0, sB>>>(x);
    cudaEventRecord(e1, sB);

    // stream 0: CSR build
    init_kernel<<<(Nn + 255)/256, 256>>>();
    convert_idx<<<eb, 256>>>(ei);
    scan_blocks<<<sb, 1024>>>();
    scan_bsums<<<1, 64>>>(sb);
    scan_add<<<(Nn + 255)/256, 256>>>();
    fill_kernel<<<eb, 256>>>();

    // join
    cudaStreamWaitEvent(0, e1, 0);

    agg1_fused<<<nb32, 256>>>(b1);
    gemm2_wmma<<<(NPAD + 127)/128, 256>>>(W2s);
    alpha2_kernel<<<nb32, 256>>>();
    agg2_fused<<<nb32, 256>>>(dout, b2);

    cudaStreamDestroy(sB);
    cudaEventDestroy(e0);
    cudaEventDestroy(e1);
}

// round 12
// speedup vs baseline: 2.2799x; 1.0239x over previous
#include <cuda_runtime.h>
#include <cuda_fp16.h>
#include <math_constants.h>
#include <mma.h>

using namespace nvcuda;

#define Nn 50000
#define Ee 800000
#define DIN 128
#define HID 32
#define HEADS 8
#define F1 (HEADS*HID)   // 256
#define NPAD 50048       // Nn rounded up to 128 (WMMA M-tile)

// ---------------- scratch (static device globals; no allocation) ----------------
__device__ __half g_hs1h[NPAD*F1];   // layer1 source features, fp16 [N,256]
__device__ __half g_aggh[NPAD*F1];   // layer1 output h, fp16 [N,256] (padded for WMMA)
__device__ __half g_hs2h[NPAD*HID];  // layer2 source features, fp16 [N,32]
__device__ float g_as1[Nn*HEADS], g_ad1[Nn*HEADS];
__device__ float g_as2[Nn], g_ad2[Nn];
__device__ float g_Wsr1[HEADS*DIN], g_Wdr1[HEADS*DIN];   // [h][k] layout
__device__ float g_Wsr2[F1], g_Wdr2[F1];
__device__ int   g_src[Ee], g_dst[Ee];     // decoded edge index (int32)
__device__ int   g_deg[Nn];                // in-degree histogram
__device__ int   g_rowptr[Nn + 1];         // CSR row pointers (by dst)
__device__ int   g_cursor[Nn];             // fill cursors
__device__ int   g_esrc[Ee];               // CSR column (src) ids
__device__ int   g_bsum[64];               // scan block sums

__device__ __forceinline__ float leaky(float v) { return v > 0.f ? v : 0.2f * v; }

__device__ __forceinline__ uint2 pack4h(float4 v) {
    __half2 h0 = __floats2half2_rn(v.x, v.y);
    __half2 h1 = __floats2half2_rn(v.z, v.w);
    uint2 r;
    r.x = *reinterpret_cast<unsigned*>(&h0);
    r.y = *reinterpret_cast<unsigned*>(&h1);
    return r;
}

// ---------------- init: zero degree histogram ----------------
__global__ void init_kernel() {
    int i = blockIdx.x * blockDim.x + threadIdx.x;
    if (i < Nn) g_deg[i] = 0;
}

// ---------------- edge index decode (int32 OR little-endian int64) + histogram ----------------
__global__ void convert_idx(const int* __restrict__ raw) {
    bool is_i64 = true;
    #pragma unroll
    for (int i = 0; i < 16; i++)
        if (raw[2*i + 1] != 0) is_i64 = false;
    int e = blockIdx.x * blockDim.x + threadIdx.x;
    if (e >= Ee) return;
    int s, d;
    if (is_i64) { s = raw[2*e]; d = raw[2*(Ee + e)]; }
    else        { s = raw[e];   d = raw[Ee + e]; }
    g_src[e] = s;
    g_dst[e] = d;
    atomicAdd(&g_deg[d], 1);
}

// ---------------- hierarchical scan ----------------
__global__ void scan_blocks() {
    __shared__ int sm[1024];
    int gid = blockIdx.x * 1024 + threadIdx.x;
    int v = (gid < Nn) ? g_deg[gid] : 0;
    sm[threadIdx.x] = v;
    __syncthreads();
    for (int off = 1; off < 1024; off <<= 1) {
        int t = (threadIdx.x >= off) ? sm[threadIdx.x - off] : 0;
        __syncthreads();
        sm[threadIdx.x] += t;
        __syncthreads();
    }
    if (gid < Nn) g_rowptr[gid] = sm[threadIdx.x] - v;
    if (threadIdx.x == 1023) g_bsum[blockIdx.x] = sm[1023];
}

__global__ void scan_bsums(int nblocks) {
    __shared__ int sm[64];
    int v = (threadIdx.x < nblocks) ? g_bsum[threadIdx.x] : 0;
    sm[threadIdx.x] = v;
    __syncthreads();
    for (int off = 1; off < 64; off <<= 1) {
        int t = (threadIdx.x >= off) ? sm[threadIdx.x - off] : 0;
        __syncthreads();
        sm[threadIdx.x] += t;
        __syncthreads();
    }
    if (threadIdx.x < nblocks) g_bsum[threadIdx.x] = sm[threadIdx.x] - v;
}

__global__ void scan_add() {
    int gid = blockIdx.x * blockDim.x + threadIdx.x;
    if (gid < Nn) {
        int r = g_rowptr[gid] + g_bsum[gid >> 10];
        g_rowptr[gid] = r;
        g_cursor[gid] = r;
    }
    if (gid == 0) g_rowptr[Nn] = Ee;
}

// ---------------- CSR fill ----------------
__global__ void fill_kernel() {
    int e = blockIdx.x * blockDim.x + threadIdx.x;
    if (e >= Ee) return;
    int pos = atomicAdd(&g_cursor[g_dst[e]], 1);
    g_esrc[pos] = g_src[e];
}

// ---------------- reduce attention weight vectors ----------------
__global__ void reduceW_kernel(const float* __restrict__ W1s, const float* __restrict__ W1d,
                               const float* __restrict__ a1s, const float* __restrict__ a1d,
                               const float* __restrict__ W2s, const float* __restrict__ W2d,
                               const float* __restrict__ a2s, const float* __restrict__ a2d) {
    int idx = blockIdx.x * blockDim.x + threadIdx.x;
    if (idx < HEADS*DIN) {
        int h = idx >> 7, k = idx & 127;
        float s = 0.f, d = 0.f;
        #pragma unroll
        for (int c = 0; c < HID; c++) {
            s += W1s[k*F1 + h*HID + c] * a1s[h*HID + c];
            d += W1d[k*F1 + h*HID + c] * a1d[h*HID + c];
        }
        g_Wsr1[h*DIN + k] = s;
        g_Wdr1[h*DIN + k] = d;
    } else if (idx < HEADS*DIN + F1) {
        int k = idx - HEADS*DIN;
        float s = 0.f, d = 0.f;
        #pragma unroll
        for (int c = 0; c < HID; c++) {
            s += W2s[k*HID + c] * a2s[c];
            d += W2d[k*HID + c] * a2d[c];
        }
        g_Wsr2[k] = s;
        g_Wdr2[k] = d;
    }
}

// ---------------- layer-1 GEMM via WMMA, K-tile 32, inline fp32->fp16 staging ----------------
// block tile 128(M) x 64(N), 8 warps 4x2, warp 32x32 (2x2 m16n16k16 frags)
__global__ void gemm1_wmma(const float* __restrict__ A, const float* __restrict__ B) {
    __shared__ __half As[128][40];       // 32 k + pad
    __shared__ __half Bs[32][72];        // 64 n + pad
    __shared__ float  Cst[8][16][20];
    int tid = threadIdx.x;
    int warp = tid >> 5, lane = tid & 31;
    int bm = blockIdx.y * 128, bn = blockIdx.x * 64;
    int wm = warp >> 1, wn = warp & 1;

    wmma::fragment<wmma::accumulator, 16, 16, 16, float> c[2][2];
    #pragma unroll
    for (int i = 0; i < 2; i++)
        #pragma unroll
        for (int j = 0; j < 2; j++)
            wmma::fill_fragment(c[i][j], 0.f);

    for (int k0 = 0; k0 < DIN; k0 += 32) {
        {
            int ar = tid >> 1, ac = (tid & 1) * 16;
            int gr = bm + ar;
            #pragma unroll
            for (int q = 0; q < 4; q++) {
                float4 v = make_float4(0.f, 0.f, 0.f, 0.f);
                if (gr < Nn) v = *reinterpret_cast<const float4*>(&A[gr*DIN + k0 + ac + q*4]);
                *reinterpret_cast<uint2*>(&As[ar][ac + q*4]) = pack4h(v);
            }
        }
        {
            int br = tid >> 3, bc = (tid & 7) * 8;
            #pragma unroll
            for (int q = 0; q < 2; q++) {
                float4 v = *reinterpret_cast<const float4*>(&B[(k0 + br)*F1 + bn + bc + q*4]);
                *reinterpret_cast<uint2*>(&Bs[br][bc + q*4]) = pack4h(v);
            }
        }
        __syncthreads();
        #pragma unroll
        for (int ks = 0; ks < 32; ks += 16) {
            wmma::fragment<wmma::matrix_a, 16, 16, 16, __half, wmma::row_major> a[2];
            wmma::fragment<wmma::matrix_b, 16, 16, 16, __half, wmma::row_major> b[2];
            #pragma unroll
            for (int i = 0; i < 2; i++)
                wmma::load_matrix_sync(a[i], &As[wm*32 + i*16][ks], 40);
            #pragma unroll
            for (int j = 0; j < 2; j++)
                wmma::load_matrix_sync(b[j], &Bs[ks][wn*32 + j*16], 72);
            #pragma unroll
            for (int i = 0; i < 2; i++)
                #pragma unroll
                for (int j = 0; j < 2; j++)
                    wmma::mma_sync(c[i][j], a[i], b[j], c[i][j]);
        }
        __syncthreads();
    }

    #pragma unroll
    for (int i = 0; i < 2; i++)
        #pragma unroll
        for (int j = 0; j < 2; j++) {
            wmma::store_matrix_sync(&Cst[warp][0][0], c[i][j], 20, wmma::mem_row_major);
            __syncwarp();
            int r = lane >> 1, cc = (lane & 1) * 8;
            int gr = bm + wm*32 + i*16 + r;
            if (gr < Nn) {
                float* p = &Cst[warp][r][cc];
                __half2 h[4];
                h[0] = __floats2half2_rn(p[0], p[1]);
                h[1] = __floats2half2_rn(p[2], p[3]);
                h[2] = __floats2half2_rn(p[4], p[5]);
                h[3] = __floats2half2_rn(p[6], p[7]);
                *reinterpret_cast<uint4*>(&g_hs1h[gr*F1 + bn + wn*32 + j*16 + cc]) =
                    *reinterpret_cast<uint4*>(h);
            }
            __syncwarp();
        }
}

// ---------------- layer-1 alphas: warp per node (fp32 x) ----------------
__global__ void alpha1_kernel(const float* __restrict__ x) {
    int warp = (blockIdx.x * blockDim.x + threadIdx.x) >> 5;
    if (warp >= Nn) return;
    int lane = threadIdx.x & 31;
    float xv0 = x[warp*DIN + lane];
    float xv1 = x[warp*DIN + 32 + lane];
    float xv2 = x[warp*DIN + 64 + lane];
    float xv3 = x[warp*DIN + 96 + lane];
    #pragma unroll
    for (int h = 0; h < HEADS; h++) {
        const float* ws = &g_Wsr1[h*DIN];
        const float* wd = &g_Wdr1[h*DIN];
        float s = xv0*ws[lane] + xv1*ws[32+lane] + xv2*ws[64+lane] + xv3*ws[96+lane];
        float d = xv0*wd[lane] + xv1*wd[32+lane] + xv2*wd[64+lane] + xv3*wd[96+lane];
        #pragma unroll
        for (int off = 16; off; off >>= 1) {
            s += __shfl_down_sync(0xffffffffu, s, off);
            d += __shfl_down_sync(0xffffffffu, d, off);
        }
        if (lane == 0) { g_as1[warp*HEADS + h] = s; g_ad1[warp*HEADS + h] = d; }
    }
}

// ---------------- layer-1 aggregate + inline softmax + fused layer-2 alphas ----------------
__device__ __forceinline__ void fma8h(float* acc, float w, uint4 u) {
    __half2 h0 = *reinterpret_cast<__half2*>(&u.x);
    __half2 h1 = *reinterpret_cast<__half2*>(&u.y);
    __half2 h2 = *reinterpret_cast<__half2*>(&u.z);
    __half2 h3 = *reinterpret_cast<__half2*>(&u.w);
    float2 f0 = __half22float2(h0);
    float2 f1 = __half22float2(h1);
    float2 f2 = __half22float2(h2);
    float2 f3 = __half22float2(h3);
    acc[0] += w*f0.x; acc[1] += w*f0.y;
    acc[2] += w*f1.x; acc[3] += w*f1.y;
    acc[4] += w*f2.x; acc[5] += w*f2.y;
    acc[6] += w*f3.x; acc[7] += w*f3.y;
}

__global__ void agg1_fused(const float* __restrict__ b1) {
    int node = (blockIdx.x * blockDim.x + threadIdx.x) >> 5;
    if (node >= Nn) return;
    int lane = threadIdx.x & 31;
    int wh = lane >> 2;
    float adv = g_ad1[node*HEADS + wh];
    int start = g_rowptr[node], end = g_rowptr[node + 1];

    float acc[8] = {};
    float wsum = 0.f;
    int j = start;
    for (; j + 2 <= end; j += 2) {
        int s0 = g_esrc[j], s1 = g_esrc[j+1];
        float w0 = __expf(leaky(g_as1[s0*HEADS + wh] + adv));
        float w1 = __expf(leaky(g_as1[s1*HEADS + wh] + adv));
        uint4 u0 = *reinterpret_cast<const uint4*>(&g_hs1h[s0*F1 + lane*8]);
        uint4 u1 = *reinterpret_cast<const uint4*>(&g_hs1h[s1*F1 + lane*8]);
        wsum += w0 + w1;
        fma8h(acc, w0, u0);
        fma8h(acc, w1, u1);
    }
    if (j < end) {
        int s0 = g_esrc[j];
        float w0 = __expf(leaky(g_as1[s0*HEADS + wh] + adv));
        uint4 u0 = *reinterpret_cast<const uint4*>(&g_hs1h[s0*F1 + lane*8]);
        wsum += w0;
        fma8h(acc, w0, u0);
    }
    float inv = 1.f / (wsum + 1e-16f);
    float4 bb0 = *reinterpret_cast<const float4*>(&b1[lane*8]);
    float4 bb1 = *reinterpret_cast<const float4*>(&b1[lane*8 + 4]);
    float o[8];
    o[0] = fmaxf(acc[0]*inv + bb0.x, 0.f); o[1] = fmaxf(acc[1]*inv + bb0.y, 0.f);
    o[2] = fmaxf(acc[2]*inv + bb0.z, 0.f); o[3] = fmaxf(acc[3]*inv + bb0.w, 0.f);
    o[4] = fmaxf(acc[4]*inv + bb1.x, 0.f); o[5] = fmaxf(acc[5]*inv + bb1.y, 0.f);
    o[6] = fmaxf(acc[6]*inv + bb1.z, 0.f); o[7] = fmaxf(acc[7]*inv + bb1.w, 0.f);
    uint2 p0 = pack4h(make_float4(o[0], o[1], o[2], o[3]));
    uint2 p1 = pack4h(make_float4(o[4], o[5], o[6], o[7]));
    *reinterpret_cast<uint4*>(&g_aggh[node*F1 + lane*8]) = make_uint4(p0.x, p0.y, p1.x, p1.y);

    // fused layer-2 alphas: dot(h, Wsr2/Wdr2) across the warp (fp32 h, pre-quantization)
    float4 ws0 = *reinterpret_cast<const float4*>(&g_Wsr2[lane*8]);
    float4 ws1 = *reinterpret_cast<const float4*>(&g_Wsr2[lane*8 + 4]);
    float4 wd0 = *reinterpret_cast<const float4*>(&g_Wdr2[lane*8]);
    float4 wd1 = *reinterpret_cast<const float4*>(&g_Wdr2[lane*8 + 4]);
    float s = o[0]*ws0.x + o[1]*ws0.y + o[2]*ws0.z + o[3]*ws0.w
            + o[4]*ws1.x + o[5]*ws1.y + o[6]*ws1.z + o[7]*ws1.w;
    float d = o[0]*wd0.x + o[1]*wd0.y + o[2]*wd0.z + o[3]*wd0.w
            + o[4]*wd1.x + o[5]*wd1.y + o[6]*wd1.z + o[7]*wd1.w;
    #pragma unroll
    for (int off = 16; off; off >>= 1) {
        s += __shfl_down_sync(0xffffffffu, s, off);
        d += __shfl_down_sync(0xffffffffu, d, off);
    }
    if (lane == 0) { g_as2[node] = s; g_ad2[node] = d; }
}

// ---------------- layer-2 GEMM via WMMA: hs2 = h[N,256] @ W2_src[256,32] ----------------
__global__ void gemm2_wmma(const float* __restrict__ W2s) {
    __shared__ __half Bs[256][40];
    __shared__ float  Cst[8][16][36];
    int tid = threadIdx.x;
    int warp = tid >> 5, lane = tid & 31;
    int bm = blockIdx.x * 128;

    {
        int row = tid;
        #pragma unroll
        for (int q = 0; q < 8; q++) {
            float4 v = *reinterpret_cast<const float4*>(&W2s[row*HID + q*4]);
            *reinterpret_cast<uint2*>(&Bs[row][q*4]) = pack4h(v);
        }
    }
    __syncthreads();

    wmma::fragment<wmma::accumulator, 16, 16, 16, float> c[2];
    wmma::fill_fragment(c[0], 0.f);
    wmma::fill_fragment(c[1], 0.f);

    const __half* arow = &g_aggh[(bm + warp*16)*F1];
    #pragma unroll
    for (int k0 = 0; k0 < F1; k0 += 16) {
        wmma::fragment<wmma::matrix_a, 16, 16, 16, __half, wmma::row_major> a;
        wmma::load_matrix_sync(a, arow + k0, F1);
        wmma::fragment<wmma::matrix_b, 16, 16, 16, __half, wmma::row_major> b0, b1;
        wmma::load_matrix_sync(b0, &Bs[k0][0], 40);
        wmma::load_matrix_sync(b1, &Bs[k0][16], 40);
        wmma::mma_sync(c[0], a, b0, c[0]);
        wmma::mma_sync(c[1], a, b1, c[1]);
    }

    wmma::store_matrix_sync(&Cst[warp][0][0],  c[0], 36, wmma::mem_row_major);
    wmma::store_matrix_sync(&Cst[warp][0][16], c[1], 36, wmma::mem_row_major);
    __syncwarp();
    int r = lane >> 1, cc = (lane & 1) * 16;
    int gr = bm + warp*16 + r;
    if (gr < Nn) {
        float* p = &Cst[warp][r][cc];
        __half2 h[8];
        #pragma unroll
        for (int q = 0; q < 8; q++) h[q] = __floats2half2_rn(p[2*q], p[2*q+1]);
        *reinterpret_cast<uint4*>(&g_hs2h[gr*HID + cc])     = *reinterpret_cast<uint4*>(h);
        *reinterpret_cast<uint4*>(&g_hs2h[gr*HID + cc + 8]) = *reinterpret_cast<uint4*>(h + 4);
    }
}

// ---------------- layer-2 aggregate with inline softmax: warp per dst node ----------------
__global__ void agg2_fused(float* __restrict__ dout, const float* __restrict__ b2) {
    int node = (blockIdx.x * blockDim.x + threadIdx.x) >> 5;
    if (node >= Nn) return;
    int lane = threadIdx.x & 31;
    float adv = g_ad2[node];
    int start = g_rowptr[node], end = g_rowptr[node + 1];
    float acc = 0.f, wsum = 0.f;
    int j = start;
    for (; j + 2 <= end; j += 2) {
        int s0 = g_esrc[j], s1 = g_esrc[j+1];
        float w0 = __expf(leaky(g_as2[s0] + adv));
        float w1 = __expf(leaky(g_as2[s1] + adv));
        float v0 = __half2float(g_hs2h[s0*HID + lane]);
        float v1 = __half2float(g_hs2h[s1*HID + lane]);
        wsum += w0 + w1;
        acc += w0*v0 + w1*v1;
    }
    if (j < end) {
        int s0 = g_esrc[j];
        float w0 = __expf(leaky(g_as2[s0] + adv));
        wsum += w0;
        acc += w0 * __half2float(g_hs2h[s0*HID + lane]);
    }
    dout[node*HID + lane] = acc / (wsum + 1e-16f) + b2[lane];
}

// ---------------- launch ----------------
extern "C" void kernel_launch(void* const* d_in, const int* in_sizes, int n_in,
                              void* d_out, int out_size) {
    const float* x   = (const float*)d_in[0];
    const int*   ei  = (const int*)d_in[1];
    const float* W1s = (const float*)d_in[2];
    const float* W1d = (const float*)d_in[3];
    const float* a1s = (const float*)d_in[4];
    const float* a1d = (const float*)d_in[5];
    const float* b1  = (const float*)d_in[6];
    const float* W2s = (const float*)d_in[7];
    const float* W2d = (const float*)d_in[8];
    const float* a2s = (const float*)d_in[9];
    const float* a2d = (const float*)d_in[10];
    const float* b2  = (const float*)d_in[11];
    float* dout = (float*)d_out;

    int eb   = (Ee + 255)/256;
    int nb32 = (Nn*32 + 255)/256;          // warp-per-node grids
    int sb   = (Nn + 1023)/1024;           // scan blocks (49)

    // Three-way fork/join inside the capture (fresh objects per call; deterministic).
    cudaStream_t sB, sC;
    cudaEvent_t e0, e1, e2;
    cudaStreamCreateWithFlags(&sB, cudaStreamNonBlocking);
    cudaStreamCreateWithFlags(&sC, cudaStreamNonBlocking);
    cudaEventCreateWithFlags(&e0, cudaEventDisableTiming);
    cudaEventCreateWithFlags(&e1, cudaEventDisableTiming);
    cudaEventCreateWithFlags(&e2, cudaEventDisableTiming);

    cudaEventRecord(e0, 0);
    cudaStreamWaitEvent(sB, e0, 0);
    cudaStreamWaitEvent(sC, e0, 0);

    // stream B: layer-1 tensor-core GEMM (inline fp16 conversion)
    dim3 g1(F1/64, (Nn + 127)/128);
    gemm1_wmma<<<g1, 256, 0, sB>>>(x, W1s);
    cudaEventRecord(e1, sB);

    // stream C: attention weight reduction + layer-1 alphas
    reduceW_kernel<<<6, 256, 0, sC>>>(W1s, W1d, a1s, a1d, W2s, W2d, a2s, a2d);
    alpha1_kernel<<<nb32, 256, 0, sC>>>(x);
    cudaEventRecord(e2, sC);

    // stream 0: CSR build
    init_kernel<<<(Nn + 255)/256, 256>>>();
    convert_idx<<<eb, 256>>>(ei);
    scan_blocks<<<sb, 1024>>>();
    scan_bsums<<<1, 64>>>(sb);
    scan_add<<<(Nn + 255)/256, 256>>>();
    fill_kernel<<<eb, 256>>>();

    // join
    cudaStreamWaitEvent(0, e1, 0);
    cudaStreamWaitEvent(0, e2, 0);

    agg1_fused<<<nb32, 256>>>(b1);          // also produces layer-2 alphas
    gemm2_wmma<<<(NPAD + 127)/128, 256>>>(W2s);
    agg2_fused<<<nb32, 256>>>(dout, b2);

    cudaStreamDestroy(sB);
    cudaStreamDestroy(sC);
    cudaEventDestroy(e0);
    cudaEventDestroy(e1);
    cudaEventDestroy(e2);
}

// round 13
// speedup vs baseline: 2.3352x; 1.0243x over previous
#include <cuda_runtime.h>
#include <cuda_fp16.h>
#include <math_constants.h>
#include <mma.h>

using namespace nvcuda;

#define Nn 50000
#define Ee 800000
#define DIN 128
#define HID 32
#define HEADS 8
#define F1 (HEADS*HID)   // 256
#define NPAD 50048       // Nn rounded up to 128 (WMMA M-tile)
#define SB 49            // scan blocks = ceil(Nn/1024)

// ---------------- scratch (static device globals; no allocation) ----------------
// NOTE: g_deg relies on zero-initialization of device globals for the first call;
// each invocation re-zeroes it (zero_deg) after scan_blocks consumes it.
__device__ __half g_hs1h[NPAD*F1];   // layer1 source features, fp16 [N,256]
__device__ __half g_aggh[NPAD*F1];   // layer1 output h, fp16 [N,256] (padded for WMMA)
__device__ __half g_hs2h[NPAD*HID];  // layer2 source features, fp16 [N,32]
__device__ float g_as1[Nn*HEADS], g_ad1[Nn*HEADS];
__device__ float g_as2[Nn], g_ad2[Nn];
__device__ float g_Wsr1[HEADS*DIN], g_Wdr1[HEADS*DIN];   // [h][k] layout
__device__ float g_Wsr2[F1], g_Wdr2[F1];
__device__ int   g_deg[Nn];                // in-degree histogram (zeroed by prev run / static init)
__device__ int   g_rowptr[Nn + 1];         // CSR row pointers (by dst)
__device__ int   g_cursor[Nn];             // fill cursors
__device__ int   g_esrc[Ee];               // CSR column (src) ids
__device__ int   g_bsum[64];               // scan block sums

__device__ __forceinline__ float leaky(float v) { return v > 0.f ? v : 0.2f * v; }

__device__ __forceinline__ uint2 pack4h(float4 v) {
    __half2 h0 = __floats2half2_rn(v.x, v.y);
    __half2 h1 = __floats2half2_rn(v.z, v.w);
    uint2 r;
    r.x = *reinterpret_cast<unsigned*>(&h0);
    r.y = *reinterpret_cast<unsigned*>(&h1);
    return r;
}

__device__ __forceinline__ bool detect_i64(const int* __restrict__ raw) {
    bool is_i64 = true;
    #pragma unroll
    for (int i = 0; i < 16; i++)
        if (raw[2*i + 1] != 0) is_i64 = false;
    return is_i64;
}

// ---------------- histogram of dst straight from raw edge buffer ----------------
__global__ void convert_hist(const int* __restrict__ raw) {
    bool is_i64 = detect_i64(raw);
    int e = blockIdx.x * blockDim.x + threadIdx.x;
    if (e >= Ee) return;
    int d = is_i64 ? raw[2*(Ee + e)] : raw[Ee + e];
    atomicAdd(&g_deg[d], 1);
}

// ---------------- per-1024-chunk scan ----------------
__global__ void scan_blocks() {
    __shared__ int sm[1024];
    int gid = blockIdx.x * 1024 + threadIdx.x;
    int v = (gid < Nn) ? g_deg[gid] : 0;
    sm[threadIdx.x] = v;
    __syncthreads();
    for (int off = 1; off < 1024; off <<= 1) {
        int t = (threadIdx.x >= off) ? sm[threadIdx.x - off] : 0;
        __syncthreads();
        sm[threadIdx.x] += t;
        __syncthreads();
    }
    if (gid < Nn) g_rowptr[gid] = sm[threadIdx.x] - v;
    if (threadIdx.x == 1023) g_bsum[blockIdx.x] = sm[1023];
}

// ---------------- re-zero degree histogram for the NEXT invocation ----------------
__global__ void zero_deg() {
    int i = blockIdx.x * blockDim.x + threadIdx.x;
    if (i < Nn) g_deg[i] = 0;
}

// ---------------- add chunk offsets (scans the 49 block sums locally) ----------------
__global__ void scan_add() {
    __shared__ int pref[64];
    int t = threadIdx.x;
    if (t < 64) pref[t] = (t < SB) ? g_bsum[t] : 0;
    __syncthreads();
    if (t == 0) {
        int run = 0;
        #pragma unroll
        for (int i = 0; i < 64; i++) { int v = pref[i]; pref[i] = run; run += v; }
    }
    __syncthreads();
    int gid = blockIdx.x * blockDim.x + t;
    if (gid < Nn) {
        int r = g_rowptr[gid] + pref[gid >> 10];
        g_rowptr[gid] = r;
        g_cursor[gid] = r;
    }
    if (gid == 0) g_rowptr[Nn] = Ee;
}

// ---------------- CSR fill: decode raw again, scatter src ids ----------------
__global__ void fill_kernel(const int* __restrict__ raw) {
    bool is_i64 = detect_i64(raw);
    int e = blockIdx.x * blockDim.x + threadIdx.x;
    if (e >= Ee) return;
    int s, d;
    if (is_i64) { s = raw[2*e]; d = raw[2*(Ee + e)]; }
    else        { s = raw[e];   d = raw[Ee + e]; }
    int pos = atomicAdd(&g_cursor[d], 1);
    g_esrc[pos] = s;
}

// ---------------- reduce attention weight vectors ----------------
__global__ void reduceW_kernel(const float* __restrict__ W1s, const float* __restrict__ W1d,
                               const float* __restrict__ a1s, const float* __restrict__ a1d,
                               const float* __restrict__ W2s, const float* __restrict__ W2d,
                               const float* __restrict__ a2s, const float* __restrict__ a2d) {
    int idx = blockIdx.x * blockDim.x + threadIdx.x;
    if (idx < HEADS*DIN) {
        int h = idx >> 7, k = idx & 127;
        float s = 0.f, d = 0.f;
        #pragma unroll
        for (int c = 0; c < HID; c++) {
            s += W1s[k*F1 + h*HID + c] * a1s[h*HID + c];
            d += W1d[k*F1 + h*HID + c] * a1d[h*HID + c];
        }
        g_Wsr1[h*DIN + k] = s;
        g_Wdr1[h*DIN + k] = d;
    } else if (idx < HEADS*DIN + F1) {
        int k = idx - HEADS*DIN;
        float s = 0.f, d = 0.f;
        #pragma unroll
        for (int c = 0; c < HID; c++) {
            s += W2s[k*HID + c] * a2s[c];
            d += W2d[k*HID + c] * a2d[c];
        }
        g_Wsr2[k] = s;
        g_Wdr2[k] = d;
    }
}

// ---------------- layer-1 GEMM via WMMA, K-tile 32, inline fp32->fp16 staging ----------------
__global__ void gemm1_wmma(const float* __restrict__ A, const float* __restrict__ B) {
    __shared__ __half As[128][40];
    __shared__ __half Bs[32][72];
    __shared__ float  Cst[8][16][20];
    int tid = threadIdx.x;
    int warp = tid >> 5, lane = tid & 31;
    int bm = blockIdx.y * 128, bn = blockIdx.x * 64;
    int wm = warp >> 1, wn = warp & 1;

    wmma::fragment<wmma::accumulator, 16, 16, 16, float> c[2][2];
    #pragma unroll
    for (int i = 0; i < 2; i++)
        #pragma unroll
        for (int j = 0; j < 2; j++)
            wmma::fill_fragment(c[i][j], 0.f);

    for (int k0 = 0; k0 < DIN; k0 += 32) {
        {
            int ar = tid >> 1, ac = (tid & 1) * 16;
            int gr = bm + ar;
            #pragma unroll
            for (int q = 0; q < 4; q++) {
                float4 v = make_float4(0.f, 0.f, 0.f, 0.f);
                if (gr < Nn) v = *reinterpret_cast<const float4*>(&A[gr*DIN + k0 + ac + q*4]);
                *reinterpret_cast<uint2*>(&As[ar][ac + q*4]) = pack4h(v);
            }
        }
        {
            int br = tid >> 3, bc = (tid & 7) * 8;
            #pragma unroll
            for (int q = 0; q < 2; q++) {
                float4 v = *reinterpret_cast<const float4*>(&B[(k0 + br)*F1 + bn + bc + q*4]);
                *reinterpret_cast<uint2*>(&Bs[br][bc + q*4]) = pack4h(v);
            }
        }
        __syncthreads();
        #pragma unroll
        for (int ks = 0; ks < 32; ks += 16) {
            wmma::fragment<wmma::matrix_a, 16, 16, 16, __half, wmma::row_major> a[2];
            wmma::fragment<wmma::matrix_b, 16, 16, 16, __half, wmma::row_major> b[2];
            #pragma unroll
            for (int i = 0; i < 2; i++)
                wmma::load_matrix_sync(a[i], &As[wm*32 + i*16][ks], 40);
            #pragma unroll
            for (int j = 0; j < 2; j++)
                wmma::load_matrix_sync(b[j], &Bs[ks][wn*32 + j*16], 72);
            #pragma unroll
            for (int i = 0; i < 2; i++)
                #pragma unroll
                for (int j = 0; j < 2; j++)
                    wmma::mma_sync(c[i][j], a[i], b[j], c[i][j]);
        }
        __syncthreads();
    }

    #pragma unroll
    for (int i = 0; i < 2; i++)
        #pragma unroll
        for (int j = 0; j < 2; j++) {
            wmma::store_matrix_sync(&Cst[warp][0][0], c[i][j], 20, wmma::mem_row_major);
            __syncwarp();
            int r = lane >> 1, cc = (lane & 1) * 8;
            int gr = bm + wm*32 + i*16 + r;
            if (gr < Nn) {
                float* p = &Cst[warp][r][cc];
                __half2 h[4];
                h[0] = __floats2half2_rn(p[0], p[1]);
                h[1] = __floats2half2_rn(p[2], p[3]);
                h[2] = __floats2half2_rn(p[4], p[5]);
                h[3] = __floats2half2_rn(p[6], p[7]);
                *reinterpret_cast<uint4*>(&g_hs1h[gr*F1 + bn + wn*32 + j*16 + cc]) =
                    *reinterpret_cast<uint4*>(h);
            }
            __syncwarp();
        }
}

// ---------------- layer-1 alphas: warp per node (fp32 x) ----------------
__global__ void alpha1_kernel(const float* __restrict__ x) {
    int warp = (blockIdx.x * blockDim.x + threadIdx.x) >> 5;
    if (warp >= Nn) return;
    int lane = threadIdx.x & 31;
    float xv0 = x[warp*DIN + lane];
    float xv1 = x[warp*DIN + 32 + lane];
    float xv2 = x[warp*DIN + 64 + lane];
    float xv3 = x[warp*DIN + 96 + lane];
    #pragma unroll
    for (int h = 0; h < HEADS; h++) {
        const float* ws = &g_Wsr1[h*DIN];
        const float* wd = &g_Wdr1[h*DIN];
        float s = xv0*ws[lane] + xv1*ws[32+lane] + xv2*ws[64+lane] + xv3*ws[96+lane];
        float d = xv0*wd[lane] + xv1*wd[32+lane] + xv2*wd[64+lane] + xv3*wd[96+lane];
        #pragma unroll
        for (int off = 16; off; off >>= 1) {
            s += __shfl_down_sync(0xffffffffu, s, off);
            d += __shfl_down_sync(0xffffffffu, d, off);
        }
        if (lane == 0) { g_as1[warp*HEADS + h] = s; g_ad1[warp*HEADS + h] = d; }
    }
}

// ---------------- layer-1 aggregate + inline softmax + fused layer-2 alphas ----------------
__device__ __forceinline__ void fma8h(float* acc, float w, uint4 u) {
    __half2 h0 = *reinterpret_cast<__half2*>(&u.x);
    __half2 h1 = *reinterpret_cast<__half2*>(&u.y);
    __half2 h2 = *reinterpret_cast<__half2*>(&u.z);
    __half2 h3 = *reinterpret_cast<__half2*>(&u.w);
    float2 f0 = __half22float2(h0);
    float2 f1 = __half22float2(h1);
    float2 f2 = __half22float2(h2);
    float2 f3 = __half22float2(h3);
    acc[0] += w*f0.x; acc[1] += w*f0.y;
    acc[2] += w*f1.x; acc[3] += w*f1.y;
    acc[4] += w*f2.x; acc[5] += w*f2.y;
    acc[6] += w*f3.x; acc[7] += w*f3.y;
}

__global__ void agg1_fused(const float* __restrict__ b1) {
    int node = (blockIdx.x * blockDim.x + threadIdx.x) >> 5;
    if (node >= Nn) return;
    int lane = threadIdx.x & 31;
    int wh = lane >> 2;
    float adv = g_ad1[node*HEADS + wh];
    int start = g_rowptr[node], end = g_rowptr[node + 1];

    float acc[8] = {};
    float wsum = 0.f;
    int j = start;
    for (; j + 2 <= end; j += 2) {
        int s0 = g_esrc[j], s1 = g_esrc[j+1];
        float w0 = __expf(leaky(g_as1[s0*HEADS + wh] + adv));
        float w1 = __expf(leaky(g_as1[s1*HEADS + wh] + adv));
        uint4 u0 = *reinterpret_cast<const uint4*>(&g_hs1h[s0*F1 + lane*8]);
        uint4 u1 = *reinterpret_cast<const uint4*>(&g_hs1h[s1*F1 + lane*8]);
        wsum += w0 + w1;
        fma8h(acc, w0, u0);
        fma8h(acc, w1, u1);
    }
    if (j < end) {
        int s0 = g_esrc[j];
        float w0 = __expf(leaky(g_as1[s0*HEADS + wh] + adv));
        uint4 u0 = *reinterpret_cast<const uint4*>(&g_hs1h[s0*F1 + lane*8]);
        wsum += w0;
        fma8h(acc, w0, u0);
    }
    float inv = 1.f / (wsum + 1e-16f);
    float4 bb0 = *reinterpret_cast<const float4*>(&b1[lane*8]);
    float4 bb1 = *reinterpret_cast<const float4*>(&b1[lane*8 + 4]);
    float o[8];
    o[0] = fmaxf(acc[0]*inv + bb0.x, 0.f); o[1] = fmaxf(acc[1]*inv + bb0.y, 0.f);
    o[2] = fmaxf(acc[2]*inv + bb0.z, 0.f); o[3] = fmaxf(acc[3]*inv + bb0.w, 0.f);
    o[4] = fmaxf(acc[4]*inv + bb1.x, 0.f); o[5] = fmaxf(acc[5]*inv + bb1.y, 0.f);
    o[6] = fmaxf(acc[6]*inv + bb1.z, 0.f); o[7] = fmaxf(acc[7]*inv + bb1.w, 0.f);
    uint2 p0 = pack4h(make_float4(o[0], o[1], o[2], o[3]));
    uint2 p1 = pack4h(make_float4(o[4], o[5], o[6], o[7]));
    *reinterpret_cast<uint4*>(&g_aggh[node*F1 + lane*8]) = make_uint4(p0.x, p0.y, p1.x, p1.y);

    // fused layer-2 alphas (fp32 h, pre-quantization)
    float4 ws0 = *reinterpret_cast<const float4*>(&g_Wsr2[lane*8]);
    float4 ws1 = *reinterpret_cast<const float4*>(&g_Wsr2[lane*8 + 4]);
    float4 wd0 = *reinterpret_cast<const float4*>(&g_Wdr2[lane*8]);
    float4 wd1 = *reinterpret_cast<const float4*>(&g_Wdr2[lane*8 + 4]);
    float s = o[0]*ws0.x + o[1]*ws0.y + o[2]*ws0.z + o[3]*ws0.w
            + o[4]*ws1.x + o[5]*ws1.y + o[6]*ws1.z + o[7]*ws1.w;
    float d = o[0]*wd0.x + o[1]*wd0.y + o[2]*wd0.z + o[3]*wd0.w
            + o[4]*wd1.x + o[5]*wd1.y + o[6]*wd1.z + o[7]*wd1.w;
    #pragma unroll
    for (int off = 16; off; off >>= 1) {
        s += __shfl_down_sync(0xffffffffu, s, off);
        d += __shfl_down_sync(0xffffffffu, d, off);
    }
    if (lane == 0) { g_as2[node] = s; g_ad2[node] = d; }
}

// ---------------- layer-2 GEMM via WMMA: hs2 = h[N,256] @ W2_src[256,32] ----------------
__global__ void gemm2_wmma(const float* __restrict__ W2s) {
    __shared__ __half Bs[256][40];
    __shared__ float  Cst[8][16][36];
    int tid = threadIdx.x;
    int warp = tid >> 5, lane = tid & 31;
    int bm = blockIdx.x * 128;

    {
        int row = tid;
        #pragma unroll
        for (int q = 0; q < 8; q++) {
            float4 v = *reinterpret_cast<const float4*>(&W2s[row*HID + q*4]);
            *reinterpret_cast<uint2*>(&Bs[row][q*4]) = pack4h(v);
        }
    }
    __syncthreads();

    wmma::fragment<wmma::accumulator, 16, 16, 16, float> c[2];
    wmma::fill_fragment(c[0], 0.f);
    wmma::fill_fragment(c[1], 0.f);

    const __half* arow = &g_aggh[(bm + warp*16)*F1];
    #pragma unroll
    for (int k0 = 0; k0 < F1; k0 += 16) {
        wmma::fragment<wmma::matrix_a, 16, 16, 16, __half, wmma::row_major> a;
        wmma::load_matrix_sync(a, arow + k0, F1);
        wmma::fragment<wmma::matrix_b, 16, 16, 16, __half, wmma::row_major> b0, b1;
        wmma::load_matrix_sync(b0, &Bs[k0][0], 40);
        wmma::load_matrix_sync(b1, &Bs[k0][16], 40);
        wmma::mma_sync(c[0], a, b0, c[0]);
        wmma::mma_sync(c[1], a, b1, c[1]);
    }

    wmma::store_matrix_sync(&Cst[warp][0][0],  c[0], 36, wmma::mem_row_major);
    wmma::store_matrix_sync(&Cst[warp][0][16], c[1], 36, wmma::mem_row_major);
    __syncwarp();
    int r = lane >> 1, cc = (lane & 1) * 16;
    int gr = bm + warp*16 + r;
    if (gr < Nn) {
        float* p = &Cst[warp][r][cc];
        __half2 h[8];
        #pragma unroll
        for (int q = 0; q < 8; q++) h[q] = __floats2half2_rn(p[2*q], p[2*q+1]);
        *reinterpret_cast<uint4*>(&g_hs2h[gr*HID + cc])     = *reinterpret_cast<uint4*>(h);
        *reinterpret_cast<uint4*>(&g_hs2h[gr*HID + cc + 8]) = *reinterpret_cast<uint4*>(h + 4);
    }
}

// ---------------- layer-2 aggregate with inline softmax: warp per dst node ----------------
__global__ void agg2_fused(float* __restrict__ dout, const float* __restrict__ b2) {
    int node = (blockIdx.x * blockDim.x + threadIdx.x) >> 5;
    if (node >= Nn) return;
    int lane = threadIdx.x & 31;
    float adv = g_ad2[node];
    int start = g_rowptr[node], end = g_rowptr[node + 1];
    float acc = 0.f, wsum = 0.f;
    int j = start;
    for (; j + 2 <= end; j += 2) {
        int s0 = g_esrc[j], s1 = g_esrc[j+1];
        float w0 = __expf(leaky(g_as2[s0] + adv));
        float w1 = __expf(leaky(g_as2[s1] + adv));
        float v0 = __half2float(g_hs2h[s0*HID + lane]);
        float v1 = __half2float(g_hs2h[s1*HID + lane]);
        wsum += w0 + w1;
        acc += w0*v0 + w1*v1;
    }
    if (j < end) {
        int s0 = g_esrc[j];
        float w0 = __expf(leaky(g_as2[s0] + adv));
        wsum += w0;
        acc += w0 * __half2float(g_hs2h[s0*HID + lane]);
    }
    dout[node*HID + lane] = acc / (wsum + 1e-16f) + b2[lane];
}

// ---------------- launch ----------------
extern "C" void kernel_launch(void* const* d_in, const int* in_sizes, int n_in,
                              void* d_out, int out_size) {
    const float* x   = (const float*)d_in[0];
    const int*   ei  = (const int*)d_in[1];
    const float* W1s = (const float*)d_in[2];
    const float* W1d = (const float*)d_in[3];
    const float* a1s = (const float*)d_in[4];
    const float* a1d = (const float*)d_in[5];
    const float* b1  = (const float*)d_in[6];
    const float* W2s = (const float*)d_in[7];
    const float* W2d = (const float*)d_in[8];
    const float* a2s = (const float*)d_in[9];
    const float* a2d = (const float*)d_in[10];
    const float* b2  = (const float*)d_in[11];
    float* dout = (float*)d_out;

    int eb   = (Ee + 255)/256;
    int nb32 = (Nn*32 + 255)/256;          // warp-per-node grids

    // Three-way fork/join inside the capture (fresh objects per call; deterministic).
    cudaStream_t sB, sC;
    cudaEvent_t e0, e1, e2, e3;
    cudaStreamCreateWithFlags(&sB, cudaStreamNonBlocking);
    cudaStreamCreateWithFlags(&sC, cudaStreamNonBlocking);
    cudaEventCreateWithFlags(&e0, cudaEventDisableTiming);
    cudaEventCreateWithFlags(&e1, cudaEventDisableTiming);
    cudaEventCreateWithFlags(&e2, cudaEventDisableTiming);
    cudaEventCreateWithFlags(&e3, cudaEventDisableTiming);

    cudaEventRecord(e0, 0);
    cudaStreamWaitEvent(sB, e0, 0);
    cudaStreamWaitEvent(sC, e0, 0);

    // stream 0: CSR build (g_deg arrives zeroed: static init on first call, zero_deg afterwards)
    convert_hist<<<eb, 256>>>(ei);
    scan_blocks<<<SB, 1024>>>();
    cudaEventRecord(e3, 0);                 // g_deg fully consumed
    scan_add<<<(Nn + 255)/256, 256>>>();
    fill_kernel<<<eb, 256>>>(ei);

    // stream B: layer-1 tensor-core GEMM, then re-zero g_deg off the critical path
    dim3 g1(F1/64, (Nn + 127)/128);
    gemm1_wmma<<<g1, 256, 0, sB>>>(x, W1s);
    cudaStreamWaitEvent(sB, e3, 0);
    zero_deg<<<(Nn + 255)/256, 256, 0, sB>>>();
    cudaEventRecord(e1, sB);

    // stream C: attention weight reduction + layer-1 alphas
    reduceW_kernel<<<6, 256, 0, sC>>>(W1s, W1d, a1s, a1d, W2s, W2d, a2s, a2d);
    alpha1_kernel<<<nb32, 256, 0, sC>>>(x);
    cudaEventRecord(e2, sC);

    // join
    cudaStreamWaitEvent(0, e1, 0);
    cudaStreamWaitEvent(0, e2, 0);

    agg1_fused<<<nb32, 256>>>(b1);          // also produces layer-2 alphas
    gemm2_wmma<<<(NPAD + 127)/128, 256>>>(W2s);
    agg2_fused<<<nb32, 256>>>(dout, b2);

    cudaStreamDestroy(sB);
    cudaStreamDestroy(sC);
    cudaEventDestroy(e0);
    cudaEventDestroy(e1);
    cudaEventDestroy(e2);
    cudaEventDestroy(e3);
}